// round 4
// baseline (speedup 1.0000x reference)
#include <cuda_runtime.h>
#include <math.h>

#define B_  4
#define T_  2048
#define D_  1024
#define H_  16
#define DH_ 64
#define FF_ 4096
#define NT  (B_*T_)   // 8192

// ---------------- scratch ----------------
__device__ float g_h  [(size_t)NT*D_];
__device__ float g_q  [(size_t)NT*D_];
__device__ float g_k  [(size_t)NT*D_];
__device__ float g_v  [(size_t)NT*D_];
__device__ float g_att[(size_t)NT*D_];
__device__ float g_x2 [(size_t)NT*D_];
__device__ float g_ff [(size_t)NT*FF_];

// ---------------- LayerNorm ----------------
__global__ void __launch_bounds__(256) ln_k(const float* __restrict__ x,
                                            const float* __restrict__ g,
                                            const float* __restrict__ b,
                                            float* __restrict__ out)
{
    __shared__ float red[2][8];
    int row = blockIdx.x;
    int tid = threadIdx.x;
    const float* xr = x + (size_t)row * D_;
    int c = tid * 4;
    float4 xv = *(const float4*)(xr + c);
    float s  = xv.x + xv.y + xv.z + xv.w;
    float ss = xv.x*xv.x + xv.y*xv.y + xv.z*xv.z + xv.w*xv.w;
    #pragma unroll
    for (int o = 16; o > 0; o >>= 1) {
        s  += __shfl_down_sync(0xffffffffu, s,  o);
        ss += __shfl_down_sync(0xffffffffu, ss, o);
    }
    if ((tid & 31) == 0) { red[0][tid >> 5] = s; red[1][tid >> 5] = ss; }
    __syncthreads();
    if (tid < 32) {
        s  = (tid < 8) ? red[0][tid] : 0.f;
        ss = (tid < 8) ? red[1][tid] : 0.f;
        #pragma unroll
        for (int o = 4; o > 0; o >>= 1) {
            s  += __shfl_down_sync(0xffffffffu, s,  o);
            ss += __shfl_down_sync(0xffffffffu, ss, o);
        }
        if (tid == 0) { red[0][0] = s; red[1][0] = ss; }
    }
    __syncthreads();
    float mean = red[0][0] * (1.f / D_);
    float var  = red[1][0] * (1.f / D_) - mean * mean;
    float rstd = rsqrtf(var + 1e-5f);
    float4 gv = *(const float4*)(g + c);
    float4 bv = *(const float4*)(b + c);
    float4 ov;
    ov.x = (xv.x - mean) * rstd * gv.x + bv.x;
    ov.y = (xv.y - mean) * rstd * gv.y + bv.y;
    ov.z = (xv.z - mean) * rstd * gv.z + bv.z;
    ov.w = (xv.w - mean) * rstd * gv.w + bv.w;
    *(float4*)(out + (size_t)row * D_ + c) = ov;
}

// ---------------- tf32 mma helper ----------------
__device__ __forceinline__ void mma_tf32(float4& c,
                                         unsigned a0, unsigned a1, unsigned a2, unsigned a3,
                                         unsigned b0, unsigned b1)
{
    asm volatile("mma.sync.aligned.m16n8k8.row.col.f32.tf32.tf32.f32 "
                 "{%0,%1,%2,%3}, {%4,%5,%6,%7}, {%8,%9}, {%0,%1,%2,%3};"
                 : "+f"(c.x), "+f"(c.y), "+f"(c.z), "+f"(c.w)
                 : "r"(a0), "r"(a1), "r"(a2), "r"(a3), "r"(b0), "r"(b1));
}

__device__ __forceinline__ void cp16(unsigned smem_addr, const float* gptr) {
    asm volatile("cp.async.cg.shared.global [%0], [%1], 16;\n"
                 :: "r"(smem_addr), "l"(gptr));
}
__device__ __forceinline__ void cp_commit() {
    asm volatile("cp.async.commit_group;\n");
}
__device__ __forceinline__ void cp_wait1() {
    asm volatile("cp.async.wait_group 1;\n");
}

// ---------------- tf32 GEMM, cp.async double-buffered ----------------
// C[M,N] = A[M,K] @ W[N,K]^T + bias (+res)(gelu). 128x128 tile, BK=32, 256 thr.
// fp32 fed raw to mma.tf32 (HW truncates to tf32).
#define SPAD 36
template<bool GELU, bool RES>
__global__ void __launch_bounds__(256) mma_gemm(const float* __restrict__ A,
                                                const float* __restrict__ W,
                                                const float* __restrict__ bias,
                                                const float* __restrict__ res,
                                                float* __restrict__ C,
                                                int M, int N, int K)
{
    __shared__ __align__(16) unsigned As[2][128 * SPAD];
    __shared__ __align__(16) unsigned Bs[2][128 * SPAD];

    int tid  = threadIdx.x;
    int warp = tid >> 5;
    int lane = tid & 31;
    int g = lane >> 2;
    int t = lane & 3;
    int wm = (warp >> 2) * 64;
    int wn = (warp & 3) * 32;

    int m0 = blockIdx.y * 128;
    int n0 = blockIdx.x * 128;

    int lrow[4], lc4[4];
    #pragma unroll
    for (int u = 0; u < 4; u++) {
        int lin = tid + u * 256;
        lrow[u] = lin >> 3;
        lc4[u]  = (lin & 7) * 4;
    }

    unsigned sA[2][4], sB[2][4];
    const float* gA[4];
    const float* gB[4];
    #pragma unroll
    for (int u = 0; u < 4; u++) {
        gA[u] = A + (size_t)(m0 + lrow[u]) * K + lc4[u];
        gB[u] = W + (size_t)(n0 + lrow[u]) * K + lc4[u];
        #pragma unroll
        for (int s = 0; s < 2; s++) {
            sA[s][u] = (unsigned)__cvta_generic_to_shared(&As[s][lrow[u] * SPAD + lc4[u]]);
            sB[s][u] = (unsigned)__cvta_generic_to_shared(&Bs[s][lrow[u] * SPAD + lc4[u]]);
        }
    }

    float4 acc[4][4];
    #pragma unroll
    for (int i = 0; i < 4; i++)
        #pragma unroll
        for (int j = 0; j < 4; j++) acc[i][j] = make_float4(0.f, 0.f, 0.f, 0.f);

    // prologue: stage 0 and stage 1
    #pragma unroll
    for (int u = 0; u < 4; u++) { cp16(sA[0][u], gA[u]); cp16(sB[0][u], gB[u]); }
    cp_commit();
    #pragma unroll
    for (int u = 0; u < 4; u++) { cp16(sA[1][u], gA[u] + 32); cp16(sB[1][u], gB[u] + 32); }
    cp_commit();

    int niter = K >> 5;
    for (int kt = 0; kt < niter; kt++) {
        cp_wait1();
        __syncthreads();
        int buf = kt & 1;
        const unsigned* Ab = As[buf];
        const unsigned* Bb = Bs[buf];

        #pragma unroll
        for (int kk = 0; kk < 32; kk += 8) {
            unsigned af[4][4];
            #pragma unroll
            for (int i = 0; i < 4; i++) {
                int r = wm + 16 * i + g;
                af[i][0] = Ab[r * SPAD + kk + t];
                af[i][1] = Ab[(r + 8) * SPAD + kk + t];
                af[i][2] = Ab[r * SPAD + kk + t + 4];
                af[i][3] = Ab[(r + 8) * SPAD + kk + t + 4];
            }
            unsigned bf[4][2];
            #pragma unroll
            for (int j = 0; j < 4; j++) {
                int cn = wn + 8 * j + g;
                bf[j][0] = Bb[cn * SPAD + kk + t];
                bf[j][1] = Bb[cn * SPAD + kk + t + 4];
            }
            #pragma unroll
            for (int i = 0; i < 4; i++)
                #pragma unroll
                for (int j = 0; j < 4; j++)
                    mma_tf32(acc[i][j], af[i][0], af[i][1], af[i][2], af[i][3],
                             bf[j][0], bf[j][1]);
        }
        __syncthreads();
        if (kt + 2 < niter) {
            int k0n = (kt + 2) * 32;
            #pragma unroll
            for (int u = 0; u < 4; u++) {
                cp16(sA[buf][u], gA[u] + k0n);
                cp16(sB[buf][u], gB[u] + k0n);
            }
        }
        cp_commit();   // empty groups keep the count consistent
    }

    // epilogue
    #pragma unroll
    for (int i = 0; i < 4; i++) {
        int r0 = m0 + wm + 16 * i + g;
        int r1 = r0 + 8;
        #pragma unroll
        for (int j = 0; j < 4; j++) {
            int col = n0 + wn + 8 * j + 2 * t;
            float b0 = bias[col], b1 = bias[col + 1];
            float v0 = acc[i][j].x + b0;
            float v1 = acc[i][j].y + b1;
            float v2 = acc[i][j].z + b0;
            float v3 = acc[i][j].w + b1;
            if (RES) {
                const float* rp0 = res + (size_t)r0 * N + col;
                const float* rp1 = res + (size_t)r1 * N + col;
                v0 += rp0[0]; v1 += rp0[1]; v2 += rp1[0]; v3 += rp1[1];
            }
            if (GELU) {
                v0 *= normcdff(v0); v1 *= normcdff(v1);
                v2 *= normcdff(v2); v3 *= normcdff(v3);
            }
            *(float2*)(C + (size_t)r0 * N + col) = make_float2(v0, v1);
            *(float2*)(C + (size_t)r1 * N + col) = make_float2(v2, v3);
        }
    }
}

// ---------------- tf32 tensor-core flash attention ----------------
#define FSPAD 68
__global__ void __launch_bounds__(128) flash_mma(const float* __restrict__ q,
                                                 const float* __restrict__ k,
                                                 const float* __restrict__ v,
                                                 float* __restrict__ o)
{
    extern __shared__ unsigned sm_u[];
    unsigned* Qs = sm_u;                    // [128][FSPAD]
    unsigned* Ks = Qs + 128 * FSPAD;        // [64][FSPAD]
    unsigned* Vt = Ks + 64 * FSPAD;         // [64][FSPAD]
    unsigned* Ps = Vt + 64 * FSPAD;         // [128][FSPAD]

    int tid  = threadIdx.x;
    int warp = tid >> 5;
    int lane = tid & 31;
    int g = lane >> 2;
    int t = lane & 3;

    int bh = blockIdx.y;
    int b  = bh >> 4;
    int h  = bh & 15;
    int qt0 = blockIdx.x * 128;
    size_t base = ((size_t)b * T_) * D_ + (size_t)h * DH_;

    {
        int rr = tid >> 4;
        int cc = (tid & 15) * 4;
        #pragma unroll
        for (int it = 0; it < 16; it++) {
            int row = rr + it * 8;
            float4 f = *(const float4*)(q + base + (size_t)(qt0 + row) * D_ + cc);
            unsigned* p = &Qs[row * FSPAD + cc];
            p[0] = __float_as_uint(f.x * 0.125f);
            p[1] = __float_as_uint(f.y * 0.125f);
            p[2] = __float_as_uint(f.z * 0.125f);
            p[3] = __float_as_uint(f.w * 0.125f);
        }
    }

    float m_i[4] = {-1e30f, -1e30f, -1e30f, -1e30f};
    float l_i[4] = {0.f, 0.f, 0.f, 0.f};
    float4 oacc[2][8];
    #pragma unroll
    for (int mb = 0; mb < 2; mb++)
        #pragma unroll
        for (int nb = 0; nb < 8; nb++) oacc[mb][nb] = make_float4(0.f, 0.f, 0.f, 0.f);

    int r0w = warp * 32;

    for (int kt0 = 0; kt0 < T_; kt0 += 64) {
        __syncthreads();
        {
            int rr = tid >> 4;
            int cc = (tid & 15) * 4;
            #pragma unroll
            for (int it = 0; it < 8; it++) {
                int row = rr + it * 8;
                float4 f = *(const float4*)(k + base + (size_t)(kt0 + row) * D_ + cc);
                unsigned* p = &Ks[row * FSPAD + cc];
                p[0] = __float_as_uint(f.x); p[1] = __float_as_uint(f.y);
                p[2] = __float_as_uint(f.z); p[3] = __float_as_uint(f.w);
            }
        }
        {
            int r  = tid & 63;
            int d0 = (tid >> 6) * 32;
            #pragma unroll
            for (int i = 0; i < 8; i++) {
                float4 f = *(const float4*)(v + base + (size_t)(kt0 + r) * D_ + d0 + 4 * i);
                Vt[(d0 + 4 * i + 0) * FSPAD + r] = __float_as_uint(f.x);
                Vt[(d0 + 4 * i + 1) * FSPAD + r] = __float_as_uint(f.y);
                Vt[(d0 + 4 * i + 2) * FSPAD + r] = __float_as_uint(f.z);
                Vt[(d0 + 4 * i + 3) * FSPAD + r] = __float_as_uint(f.w);
            }
        }
        __syncthreads();

        float4 sacc[2][8];
        #pragma unroll
        for (int mb = 0; mb < 2; mb++)
            #pragma unroll
            for (int nb = 0; nb < 8; nb++) sacc[mb][nb] = make_float4(0.f, 0.f, 0.f, 0.f);
        #pragma unroll
        for (int kk = 0; kk < 8; kk++) {
            unsigned a[2][4];
            #pragma unroll
            for (int mb = 0; mb < 2; mb++) {
                int r = r0w + mb * 16 + g;
                a[mb][0] = Qs[r * FSPAD + kk * 8 + t];
                a[mb][1] = Qs[(r + 8) * FSPAD + kk * 8 + t];
                a[mb][2] = Qs[r * FSPAD + kk * 8 + t + 4];
                a[mb][3] = Qs[(r + 8) * FSPAD + kk * 8 + t + 4];
            }
            unsigned bb[8][2];
            #pragma unroll
            for (int nb = 0; nb < 8; nb++) {
                bb[nb][0] = Ks[(nb * 8 + g) * FSPAD + kk * 8 + t];
                bb[nb][1] = Ks[(nb * 8 + g) * FSPAD + kk * 8 + t + 4];
            }
            #pragma unroll
            for (int mb = 0; mb < 2; mb++)
                #pragma unroll
                for (int nb = 0; nb < 8; nb++)
                    mma_tf32(sacc[mb][nb], a[mb][0], a[mb][1], a[mb][2], a[mb][3],
                             bb[nb][0], bb[nb][1]);
        }

        #pragma unroll
        for (int mb = 0; mb < 2; mb++) {
            float mx0 = -1e30f, mx1 = -1e30f;
            #pragma unroll
            for (int nb = 0; nb < 8; nb++) {
                mx0 = fmaxf(mx0, fmaxf(sacc[mb][nb].x, sacc[mb][nb].y));
                mx1 = fmaxf(mx1, fmaxf(sacc[mb][nb].z, sacc[mb][nb].w));
            }
            mx0 = fmaxf(mx0, __shfl_xor_sync(0xffffffffu, mx0, 1));
            mx0 = fmaxf(mx0, __shfl_xor_sync(0xffffffffu, mx0, 2));
            mx1 = fmaxf(mx1, __shfl_xor_sync(0xffffffffu, mx1, 1));
            mx1 = fmaxf(mx1, __shfl_xor_sync(0xffffffffu, mx1, 2));

            float mn0 = fmaxf(m_i[2 * mb + 0], mx0);
            float mn1 = fmaxf(m_i[2 * mb + 1], mx1);
            float al0 = __expf(m_i[2 * mb + 0] - mn0);
            float al1 = __expf(m_i[2 * mb + 1] - mn1);
            m_i[2 * mb + 0] = mn0;
            m_i[2 * mb + 1] = mn1;

            float s0 = 0.f, s1 = 0.f;
            int rbase = (r0w + mb * 16 + g) * FSPAD;
            int rbase8 = (r0w + mb * 16 + g + 8) * FSPAD;
            #pragma unroll
            for (int nb = 0; nb < 8; nb++) {
                float p0 = __expf(sacc[mb][nb].x - mn0);
                float p1 = __expf(sacc[mb][nb].y - mn0);
                float p2 = __expf(sacc[mb][nb].z - mn1);
                float p3 = __expf(sacc[mb][nb].w - mn1);
                s0 += p0 + p1; s1 += p2 + p3;
                int cc = nb * 8 + 2 * t;
                Ps[rbase + cc]      = __float_as_uint(p0);
                Ps[rbase + cc + 1]  = __float_as_uint(p1);
                Ps[rbase8 + cc]     = __float_as_uint(p2);
                Ps[rbase8 + cc + 1] = __float_as_uint(p3);
            }
            s0 += __shfl_xor_sync(0xffffffffu, s0, 1);
            s0 += __shfl_xor_sync(0xffffffffu, s0, 2);
            s1 += __shfl_xor_sync(0xffffffffu, s1, 1);
            s1 += __shfl_xor_sync(0xffffffffu, s1, 2);
            l_i[2 * mb + 0] = l_i[2 * mb + 0] * al0 + s0;
            l_i[2 * mb + 1] = l_i[2 * mb + 1] * al1 + s1;

            #pragma unroll
            for (int nb = 0; nb < 8; nb++) {
                oacc[mb][nb].x *= al0; oacc[mb][nb].y *= al0;
                oacc[mb][nb].z *= al1; oacc[mb][nb].w *= al1;
            }
        }
        __syncwarp();

        #pragma unroll
        for (int kk = 0; kk < 8; kk++) {
            unsigned a[2][4];
            #pragma unroll
            for (int mb = 0; mb < 2; mb++) {
                int r = r0w + mb * 16 + g;
                a[mb][0] = Ps[r * FSPAD + kk * 8 + t];
                a[mb][1] = Ps[(r + 8) * FSPAD + kk * 8 + t];
                a[mb][2] = Ps[r * FSPAD + kk * 8 + t + 4];
                a[mb][3] = Ps[(r + 8) * FSPAD + kk * 8 + t + 4];
            }
            unsigned bb[8][2];
            #pragma unroll
            for (int nb = 0; nb < 8; nb++) {
                bb[nb][0] = Vt[(nb * 8 + g) * FSPAD + kk * 8 + t];
                bb[nb][1] = Vt[(nb * 8 + g) * FSPAD + kk * 8 + t + 4];
            }
            #pragma unroll
            for (int mb = 0; mb < 2; mb++)
                #pragma unroll
                for (int nb = 0; nb < 8; nb++)
                    mma_tf32(oacc[mb][nb], a[mb][0], a[mb][1], a[mb][2], a[mb][3],
                             bb[nb][0], bb[nb][1]);
        }
    }

    #pragma unroll
    for (int mb = 0; mb < 2; mb++) {
        float inv0 = 1.f / l_i[2 * mb + 0];
        float inv1 = 1.f / l_i[2 * mb + 1];
        int row0 = qt0 + r0w + mb * 16 + g;
        int row1 = row0 + 8;
        #pragma unroll
        for (int nb = 0; nb < 8; nb++) {
            int cc = nb * 8 + 2 * t;
            *(float2*)(o + base + (size_t)row0 * D_ + cc) =
                make_float2(oacc[mb][nb].x * inv0, oacc[mb][nb].y * inv0);
            *(float2*)(o + base + (size_t)row1 * D_ + cc) =
                make_float2(oacc[mb][nb].z * inv1, oacc[mb][nb].w * inv1);
        }
    }
}

// ---------------- launch ----------------
extern "C" void kernel_launch(void* const* d_in, const int* in_sizes, int n_in,
                              void* d_out, int out_size)
{
    const float* x    = (const float*)d_in[0];
    const float* ln1g = (const float*)d_in[1];
    const float* ln1b = (const float*)d_in[2];
    const float* ln2g = (const float*)d_in[3];
    const float* ln2b = (const float*)d_in[4];
    const float* wq   = (const float*)d_in[5];
    const float* bq   = (const float*)d_in[6];
    const float* wk   = (const float*)d_in[7];
    const float* bk   = (const float*)d_in[8];
    const float* wv   = (const float*)d_in[9];
    const float* bv   = (const float*)d_in[10];
    const float* wo   = (const float*)d_in[11];
    const float* bo   = (const float*)d_in[12];
    const float* w1   = (const float*)d_in[13];
    const float* b1   = (const float*)d_in[14];
    const float* w2   = (const float*)d_in[15];
    const float* b2   = (const float*)d_in[16];
    float* out = (float*)d_out;

    void* p;
    cudaGetSymbolAddress(&p, g_h);   float* h   = (float*)p;
    cudaGetSymbolAddress(&p, g_q);   float* qb  = (float*)p;
    cudaGetSymbolAddress(&p, g_k);   float* kb  = (float*)p;
    cudaGetSymbolAddress(&p, g_v);   float* vb  = (float*)p;
    cudaGetSymbolAddress(&p, g_att); float* att = (float*)p;
    cudaGetSymbolAddress(&p, g_x2);  float* x2  = (float*)p;
    cudaGetSymbolAddress(&p, g_ff);  float* ff  = (float*)p;

    int flash_smem = (128 + 64 + 64 + 128) * FSPAD * (int)sizeof(unsigned);
    cudaFuncSetAttribute(flash_mma, cudaFuncAttributeMaxDynamicSharedMemorySize, flash_smem);

    dim3 gD(D_ / 128, NT / 128);    // (8, 64)
    dim3 gF(FF_ / 128, NT / 128);   // (32, 64)

    ln_k<<<NT, 256>>>(x, ln1g, ln1b, h);
    mma_gemm<false, false><<<gD, 256>>>(h, wq, bq, nullptr, qb, NT, D_, D_);
    mma_gemm<false, false><<<gD, 256>>>(h, wk, bk, nullptr, kb, NT, D_, D_);
    mma_gemm<false, false><<<gD, 256>>>(h, wv, bv, nullptr, vb, NT, D_, D_);
    flash_mma<<<dim3(T_ / 128, B_ * H_), 128, flash_smem>>>(qb, kb, vb, att);
    mma_gemm<false, true><<<gD, 256>>>(att, wo, bo, x, x2, NT, D_, D_);
    ln_k<<<NT, 256>>>(x2, ln2g, ln2b, h);
    mma_gemm<true, false><<<gF, 256>>>(h, w1, b1, nullptr, ff, NT, FF_, D_);
    mma_gemm<false, true><<<gD, 256>>>(ff, w2, b2, x2, out, NT, D_, FF_);
}

// round 6
// speedup vs baseline: 1.6763x; 1.6763x over previous
#include <cuda_runtime.h>
#include <cuda_fp16.h>
#include <math.h>
#include <stdint.h>

#define B_  4
#define T_  2048
#define D_  1024
#define H_  16
#define DH_ 64
#define FF_ 4096
#define NT  (B_*T_)   // 8192

// ---------------- scratch (halves for mma operands, fp32 residual stream) ------
__device__ __half g_hh [(size_t)NT*D_];
__device__ __half g_qh [(size_t)NT*D_];
__device__ __half g_kh [(size_t)NT*D_];
__device__ __half g_vh [(size_t)NT*D_];
__device__ __half g_ah [(size_t)NT*D_];
__device__ __half g_fh [(size_t)NT*FF_];
__device__ float  g_x2 [(size_t)NT*D_];
__device__ __half g_wh [(size_t)12*1024*1024];

// ---------------- weight fp32 -> fp16 ----------------
__global__ void __launch_bounds__(256) w2h_k(const float* __restrict__ src,
                                             __half* __restrict__ dst, int n4)
{
    int i = blockIdx.x * 256 + threadIdx.x;
    if (i < n4) {
        float4 v = ((const float4*)src)[i];
        *(half2*)(dst + (size_t)i * 4)     = __floats2half2_rn(v.x, v.y);
        *(half2*)(dst + (size_t)i * 4 + 2) = __floats2half2_rn(v.z, v.w);
    }
}

// ---------------- LayerNorm: fp32 in, fp16 out ----------------
__global__ void __launch_bounds__(256) ln_k(const float* __restrict__ x,
                                            const float* __restrict__ g,
                                            const float* __restrict__ b,
                                            __half* __restrict__ out)
{
    __shared__ float red[2][8];
    int row = blockIdx.x;
    int tid = threadIdx.x;
    const float* xr = x + (size_t)row * D_;
    int c = tid * 4;
    float4 xv = *(const float4*)(xr + c);
    float s  = xv.x + xv.y + xv.z + xv.w;
    float ss = xv.x*xv.x + xv.y*xv.y + xv.z*xv.z + xv.w*xv.w;
    #pragma unroll
    for (int o = 16; o > 0; o >>= 1) {
        s  += __shfl_down_sync(0xffffffffu, s,  o);
        ss += __shfl_down_sync(0xffffffffu, ss, o);
    }
    if ((tid & 31) == 0) { red[0][tid >> 5] = s; red[1][tid >> 5] = ss; }
    __syncthreads();
    if (tid < 32) {
        s  = (tid < 8) ? red[0][tid] : 0.f;
        ss = (tid < 8) ? red[1][tid] : 0.f;
        #pragma unroll
        for (int o = 4; o > 0; o >>= 1) {
            s  += __shfl_down_sync(0xffffffffu, s,  o);
            ss += __shfl_down_sync(0xffffffffu, ss, o);
        }
        if (tid == 0) { red[0][0] = s; red[1][0] = ss; }
    }
    __syncthreads();
    float mean = red[0][0] * (1.f / D_);
    float var  = red[1][0] * (1.f / D_) - mean * mean;
    float rstd = rsqrtf(var + 1e-5f);
    float4 gv = *(const float4*)(g + c);
    float4 bv = *(const float4*)(b + c);
    float o0 = (xv.x - mean) * rstd * gv.x + bv.x;
    float o1 = (xv.y - mean) * rstd * gv.y + bv.y;
    float o2 = (xv.z - mean) * rstd * gv.z + bv.z;
    float o3 = (xv.w - mean) * rstd * gv.w + bv.w;
    *(half2*)(out + (size_t)row * D_ + c)     = __floats2half2_rn(o0, o1);
    *(half2*)(out + (size_t)row * D_ + c + 2) = __floats2half2_rn(o2, o3);
}

// ---------------- fp16 mma helper (m16n8k16) ----------------
__device__ __forceinline__ void mma_f16(float4& c,
                                        unsigned a0, unsigned a1, unsigned a2, unsigned a3,
                                        unsigned b0, unsigned b1)
{
    asm volatile("mma.sync.aligned.m16n8k16.row.col.f32.f16.f16.f32 "
                 "{%0,%1,%2,%3}, {%4,%5,%6,%7}, {%8,%9}, {%0,%1,%2,%3};"
                 : "+f"(c.x), "+f"(c.y), "+f"(c.z), "+f"(c.w)
                 : "r"(a0), "r"(a1), "r"(a2), "r"(a3), "r"(b0), "r"(b1));
}

// ---------------- fp16 GEMM: C[M,N] = A[M,K] @ W[N,K]^T + bias (+res)(gelu) ------
// 128x128 tile, BK=32, 256 threads (8 warps 2x4), warp tile 64x32.
#define SPADH 40
template<bool GELU, bool RES, bool HOUT>
__global__ void __launch_bounds__(256) hgemm(const __half* __restrict__ A,
                                             const __half* __restrict__ W,
                                             const float* __restrict__ bias,
                                             const float* __restrict__ res,
                                             float* __restrict__ Cf,
                                             __half* __restrict__ Ch,
                                             int M, int N, int K)
{
    __shared__ __half As[128 * SPADH];
    __shared__ __half Bs[128 * SPADH];

    int tid  = threadIdx.x;
    int warp = tid >> 5;
    int lane = tid & 31;
    int g = lane >> 2;
    int t = lane & 3;
    int wm = (warp >> 2) * 64;
    int wn = (warp & 3) * 32;

    int m0 = blockIdx.y * 128;
    int n0 = blockIdx.x * 128;

    int lrow[2], lcb[2];
    #pragma unroll
    for (int u = 0; u < 2; u++) {
        int lin = tid + u * 256;
        lrow[u] = lin >> 2;
        lcb[u]  = (lin & 3) * 8;
    }

    float4 acc[4][4];
    #pragma unroll
    for (int i = 0; i < 4; i++)
        #pragma unroll
        for (int j = 0; j < 4; j++) acc[i][j] = make_float4(0.f, 0.f, 0.f, 0.f);

    uint4 rA[2], rB[2];
    #pragma unroll
    for (int u = 0; u < 2; u++) {
        rA[u] = *(const uint4*)(A + (size_t)(m0 + lrow[u]) * K + lcb[u]);
        rB[u] = *(const uint4*)(W + (size_t)(n0 + lrow[u]) * K + lcb[u]);
    }

    for (int k0 = 0; k0 < K; k0 += 32) {
        #pragma unroll
        for (int u = 0; u < 2; u++) {
            *(uint4*)&As[lrow[u] * SPADH + lcb[u]] = rA[u];
            *(uint4*)&Bs[lrow[u] * SPADH + lcb[u]] = rB[u];
        }
        __syncthreads();
        if (k0 + 32 < K) {
            #pragma unroll
            for (int u = 0; u < 2; u++) {
                rA[u] = *(const uint4*)(A + (size_t)(m0 + lrow[u]) * K + k0 + 32 + lcb[u]);
                rB[u] = *(const uint4*)(W + (size_t)(n0 + lrow[u]) * K + k0 + 32 + lcb[u]);
            }
        }
        #pragma unroll
        for (int kk = 0; kk < 32; kk += 16) {
            unsigned af[4][4];
            #pragma unroll
            for (int i = 0; i < 4; i++) {
                int r = wm + 16 * i + g;
                af[i][0] = *(const unsigned*)&As[r * SPADH + kk + 2 * t];
                af[i][1] = *(const unsigned*)&As[(r + 8) * SPADH + kk + 2 * t];
                af[i][2] = *(const unsigned*)&As[r * SPADH + kk + 8 + 2 * t];
                af[i][3] = *(const unsigned*)&As[(r + 8) * SPADH + kk + 8 + 2 * t];
            }
            unsigned bf[4][2];
            #pragma unroll
            for (int j = 0; j < 4; j++) {
                int cn = wn + 8 * j + g;
                bf[j][0] = *(const unsigned*)&Bs[cn * SPADH + kk + 2 * t];
                bf[j][1] = *(const unsigned*)&Bs[cn * SPADH + kk + 8 + 2 * t];
            }
            #pragma unroll
            for (int i = 0; i < 4; i++)
                #pragma unroll
                for (int j = 0; j < 4; j++)
                    mma_f16(acc[i][j], af[i][0], af[i][1], af[i][2], af[i][3],
                            bf[j][0], bf[j][1]);
        }
        __syncthreads();
    }

    #pragma unroll
    for (int i = 0; i < 4; i++) {
        int r0 = m0 + wm + 16 * i + g;
        int r1 = r0 + 8;
        #pragma unroll
        for (int j = 0; j < 4; j++) {
            int col = n0 + wn + 8 * j + 2 * t;
            float b0 = bias[col], b1 = bias[col + 1];
            float v0 = acc[i][j].x + b0;
            float v1 = acc[i][j].y + b1;
            float v2 = acc[i][j].z + b0;
            float v3 = acc[i][j].w + b1;
            if (RES) {
                const float* rp0 = res + (size_t)r0 * N + col;
                const float* rp1 = res + (size_t)r1 * N + col;
                v0 += rp0[0]; v1 += rp0[1]; v2 += rp1[0]; v3 += rp1[1];
            }
            if (GELU) {
                v0 *= normcdff(v0); v1 *= normcdff(v1);
                v2 *= normcdff(v2); v3 *= normcdff(v3);
            }
            if (HOUT) {
                *(half2*)(Ch + (size_t)r0 * N + col) = __floats2half2_rn(v0, v1);
                *(half2*)(Ch + (size_t)r1 * N + col) = __floats2half2_rn(v2, v3);
            } else {
                *(float2*)(Cf + (size_t)r0 * N + col) = make_float2(v0, v1);
                *(float2*)(Cf + (size_t)r1 * N + col) = make_float2(v2, v3);
            }
        }
    }
}

// ---------------- fp16 flash attention (m16n8k16) ----------------
// 128 queries/CTA, 4 warps x 32 rows, 64-key tiles, fp32 online softmax.
#define FSP 72
__global__ void __launch_bounds__(128) flash_h(const __half* __restrict__ q,
                                               const __half* __restrict__ k,
                                               const __half* __restrict__ v,
                                               __half* __restrict__ o)
{
    extern __shared__ __half smh[];
    __half* Qs = smh;                  // [128][FSP]
    __half* Ks = Qs + 128 * FSP;       // [64][FSP]
    __half* Vt = Ks + 64 * FSP;        // [64][FSP]  (dh-major)
    __half* Ps = Vt + 64 * FSP;        // [128][FSP]

    int tid  = threadIdx.x;
    int warp = tid >> 5;
    int lane = tid & 31;
    int g = lane >> 2;
    int t = lane & 3;

    int bh = blockIdx.y;
    int b  = bh >> 4;
    int h  = bh & 15;
    int qt0 = blockIdx.x * 128;
    size_t base = ((size_t)b * T_) * D_ + (size_t)h * DH_;

    // Q tile (scaled by 1/8)
    {
        half2 sc = __float2half2_rn(0.125f);
        #pragma unroll
        for (int it = 0; it < 8; it++) {
            int lin = tid + it * 128;
            int row = lin >> 3;
            int cb  = (lin & 7) * 8;
            uint4 u = *(const uint4*)(q + base + (size_t)(qt0 + row) * D_ + cb);
            half2* hp = (half2*)&u;
            hp[0] = __hmul2(hp[0], sc); hp[1] = __hmul2(hp[1], sc);
            hp[2] = __hmul2(hp[2], sc); hp[3] = __hmul2(hp[3], sc);
            *(uint4*)&Qs[row * FSP + cb] = u;
        }
    }

    float m_i[4] = {-1e30f, -1e30f, -1e30f, -1e30f};
    float l_i[4] = {0.f, 0.f, 0.f, 0.f};
    float4 oacc[2][8];
    #pragma unroll
    for (int mb = 0; mb < 2; mb++)
        #pragma unroll
        for (int nb = 0; nb < 8; nb++) oacc[mb][nb] = make_float4(0.f, 0.f, 0.f, 0.f);

    int r0w = warp * 32;

    for (int kt0 = 0; kt0 < T_; kt0 += 64) {
        __syncthreads();
        // K tile
        #pragma unroll
        for (int it = 0; it < 4; it++) {
            int lin = tid + it * 128;
            int row = lin >> 3;
            int cb  = (lin & 7) * 8;
            *(uint4*)&Ks[row * FSP + cb] =
                *(const uint4*)(k + base + (size_t)(kt0 + row) * D_ + cb);
        }
        // V tile transposed
        {
            int r  = tid & 63;
            int d0 = (tid >> 6) * 32;
            #pragma unroll
            for (int i = 0; i < 4; i++) {
                uint4 u = *(const uint4*)(v + base + (size_t)(kt0 + r) * D_ + d0 + 8 * i);
                const __half* hp = (const __half*)&u;
                #pragma unroll
                for (int e = 0; e < 8; e++)
                    Vt[(d0 + 8 * i + e) * FSP + r] = hp[e];
            }
        }
        __syncthreads();

        // S = Q @ K^T (32x64 per warp)
        float4 sacc[2][8];
        #pragma unroll
        for (int mb = 0; mb < 2; mb++)
            #pragma unroll
            for (int nb = 0; nb < 8; nb++) sacc[mb][nb] = make_float4(0.f, 0.f, 0.f, 0.f);
        #pragma unroll
        for (int ks = 0; ks < 4; ks++) {
            unsigned a[2][4];
            #pragma unroll
            for (int mb = 0; mb < 2; mb++) {
                int r = r0w + mb * 16 + g;
                a[mb][0] = *(const unsigned*)&Qs[r * FSP + ks * 16 + 2 * t];
                a[mb][1] = *(const unsigned*)&Qs[(r + 8) * FSP + ks * 16 + 2 * t];
                a[mb][2] = *(const unsigned*)&Qs[r * FSP + ks * 16 + 8 + 2 * t];
                a[mb][3] = *(const unsigned*)&Qs[(r + 8) * FSP + ks * 16 + 8 + 2 * t];
            }
            unsigned bb[8][2];
            #pragma unroll
            for (int nb = 0; nb < 8; nb++) {
                bb[nb][0] = *(const unsigned*)&Ks[(nb * 8 + g) * FSP + ks * 16 + 2 * t];
                bb[nb][1] = *(const unsigned*)&Ks[(nb * 8 + g) * FSP + ks * 16 + 8 + 2 * t];
            }
            #pragma unroll
            for (int mb = 0; mb < 2; mb++)
                #pragma unroll
                for (int nb = 0; nb < 8; nb++)
                    mma_f16(sacc[mb][nb], a[mb][0], a[mb][1], a[mb][2], a[mb][3],
                            bb[nb][0], bb[nb][1]);
        }

        // online softmax on fragments; write P (half) to Ps
        #pragma unroll
        for (int mb = 0; mb < 2; mb++) {
            float mx0 = -1e30f, mx1 = -1e30f;
            #pragma unroll
            for (int nb = 0; nb < 8; nb++) {
                mx0 = fmaxf(mx0, fmaxf(sacc[mb][nb].x, sacc[mb][nb].y));
                mx1 = fmaxf(mx1, fmaxf(sacc[mb][nb].z, sacc[mb][nb].w));
            }
            mx0 = fmaxf(mx0, __shfl_xor_sync(0xffffffffu, mx0, 1));
            mx0 = fmaxf(mx0, __shfl_xor_sync(0xffffffffu, mx0, 2));
            mx1 = fmaxf(mx1, __shfl_xor_sync(0xffffffffu, mx1, 1));
            mx1 = fmaxf(mx1, __shfl_xor_sync(0xffffffffu, mx1, 2));

            float mn0 = fmaxf(m_i[2 * mb + 0], mx0);
            float mn1 = fmaxf(m_i[2 * mb + 1], mx1);
            float al0 = __expf(m_i[2 * mb + 0] - mn0);
            float al1 = __expf(m_i[2 * mb + 1] - mn1);
            m_i[2 * mb + 0] = mn0;
            m_i[2 * mb + 1] = mn1;

            float s0 = 0.f, s1 = 0.f;
            int rbase  = (r0w + mb * 16 + g) * FSP;
            int rbase8 = (r0w + mb * 16 + g + 8) * FSP;
            #pragma unroll
            for (int nb = 0; nb < 8; nb++) {
                float p0 = __expf(sacc[mb][nb].x - mn0);
                float p1 = __expf(sacc[mb][nb].y - mn0);
                float p2 = __expf(sacc[mb][nb].z - mn1);
                float p3 = __expf(sacc[mb][nb].w - mn1);
                s0 += p0 + p1; s1 += p2 + p3;
                int cc = nb * 8 + 2 * t;
                *(half2*)&Ps[rbase + cc]  = __floats2half2_rn(p0, p1);
                *(half2*)&Ps[rbase8 + cc] = __floats2half2_rn(p2, p3);
            }
            s0 += __shfl_xor_sync(0xffffffffu, s0, 1);
            s0 += __shfl_xor_sync(0xffffffffu, s0, 2);
            s1 += __shfl_xor_sync(0xffffffffu, s1, 1);
            s1 += __shfl_xor_sync(0xffffffffu, s1, 2);
            l_i[2 * mb + 0] = l_i[2 * mb + 0] * al0 + s0;
            l_i[2 * mb + 1] = l_i[2 * mb + 1] * al1 + s1;

            #pragma unroll
            for (int nb = 0; nb < 8; nb++) {
                oacc[mb][nb].x *= al0; oacc[mb][nb].y *= al0;
                oacc[mb][nb].z *= al1; oacc[mb][nb].w *= al1;
            }
        }
        __syncwarp();

        // O += P @ V
        #pragma unroll
        for (int ks = 0; ks < 4; ks++) {
            unsigned a[2][4];
            #pragma unroll
            for (int mb = 0; mb < 2; mb++) {
                int r = r0w + mb * 16 + g;
                a[mb][0] = *(const unsigned*)&Ps[r * FSP + ks * 16 + 2 * t];
                a[mb][1] = *(const unsigned*)&Ps[(r + 8) * FSP + ks * 16 + 2 * t];
                a[mb][2] = *(const unsigned*)&Ps[r * FSP + ks * 16 + 8 + 2 * t];
                a[mb][3] = *(const unsigned*)&Ps[(r + 8) * FSP + ks * 16 + 8 + 2 * t];
            }
            unsigned bb[8][2];
            #pragma unroll
            for (int nb = 0; nb < 8; nb++) {
                bb[nb][0] = *(const unsigned*)&Vt[(nb * 8 + g) * FSP + ks * 16 + 2 * t];
                bb[nb][1] = *(const unsigned*)&Vt[(nb * 8 + g) * FSP + ks * 16 + 8 + 2 * t];
            }
            #pragma unroll
            for (int mb = 0; mb < 2; mb++)
                #pragma unroll
                for (int nb = 0; nb < 8; nb++)
                    mma_f16(oacc[mb][nb], a[mb][0], a[mb][1], a[mb][2], a[mb][3],
                            bb[nb][0], bb[nb][1]);
        }
    }

    // epilogue
    #pragma unroll
    for (int mb = 0; mb < 2; mb++) {
        float inv0 = 1.f / l_i[2 * mb + 0];
        float inv1 = 1.f / l_i[2 * mb + 1];
        int row0 = qt0 + r0w + mb * 16 + g;
        int row1 = row0 + 8;
        #pragma unroll
        for (int nb = 0; nb < 8; nb++) {
            int cc = nb * 8 + 2 * t;
            *(half2*)(o + base + (size_t)row0 * D_ + cc) =
                __floats2half2_rn(oacc[mb][nb].x * inv0, oacc[mb][nb].y * inv0);
            *(half2*)(o + base + (size_t)row1 * D_ + cc) =
                __floats2half2_rn(oacc[mb][nb].z * inv1, oacc[mb][nb].w * inv1);
        }
    }
}

// ---------------- launch ----------------
extern "C" void kernel_launch(void* const* d_in, const int* in_sizes, int n_in,
                              void* d_out, int out_size)
{
    const float* x    = (const float*)d_in[0];
    const float* ln1g = (const float*)d_in[1];
    const float* ln1b = (const float*)d_in[2];
    const float* ln2g = (const float*)d_in[3];
    const float* ln2b = (const float*)d_in[4];
    const float* wq   = (const float*)d_in[5];
    const float* bq   = (const float*)d_in[6];
    const float* wk   = (const float*)d_in[7];
    const float* bk   = (const float*)d_in[8];
    const float* wv   = (const float*)d_in[9];
    const float* bv   = (const float*)d_in[10];
    const float* wo   = (const float*)d_in[11];
    const float* bo   = (const float*)d_in[12];
    const float* w1   = (const float*)d_in[13];
    const float* b1   = (const float*)d_in[14];
    const float* w2   = (const float*)d_in[15];
    const float* b2   = (const float*)d_in[16];
    float* out = (float*)d_out;

    void* p;
    cudaGetSymbolAddress(&p, g_hh); __half* h   = (__half*)p;
    cudaGetSymbolAddress(&p, g_qh); __half* qb  = (__half*)p;
    cudaGetSymbolAddress(&p, g_kh); __half* kb  = (__half*)p;
    cudaGetSymbolAddress(&p, g_vh); __half* vb  = (__half*)p;
    cudaGetSymbolAddress(&p, g_ah); __half* att = (__half*)p;
    cudaGetSymbolAddress(&p, g_fh); __half* ff  = (__half*)p;
    cudaGetSymbolAddress(&p, g_x2); float*  x2  = (float*)p;
    cudaGetSymbolAddress(&p, g_wh); __half* wh  = (__half*)p;

    const size_t MB1 = 1024 * 1024;
    __half* hwq = wh;
    __half* hwk = wh + 1 * MB1;
    __half* hwv = wh + 2 * MB1;
    __half* hwo = wh + 3 * MB1;
    __half* hw1 = wh + 4 * MB1;
    __half* hw2 = wh + 8 * MB1;

    int flash_smem = (128 + 64 + 64 + 128) * FSP * (int)sizeof(__half);
    cudaFuncSetAttribute(flash_h, cudaFuncAttributeMaxDynamicSharedMemorySize, flash_smem);

    // weights -> fp16 (deterministic each call)
    w2h_k<<<(int)(1 * MB1 / 4 + 255) / 256, 256>>>(wq, hwq, (int)(1 * MB1 / 4));
    w2h_k<<<(int)(1 * MB1 / 4 + 255) / 256, 256>>>(wk, hwk, (int)(1 * MB1 / 4));
    w2h_k<<<(int)(1 * MB1 / 4 + 255) / 256, 256>>>(wv, hwv, (int)(1 * MB1 / 4));
    w2h_k<<<(int)(1 * MB1 / 4 + 255) / 256, 256>>>(wo, hwo, (int)(1 * MB1 / 4));
    w2h_k<<<(int)(4 * MB1 / 4 + 255) / 256, 256>>>(w1, hw1, (int)(4 * MB1 / 4));
    w2h_k<<<(int)(4 * MB1 / 4 + 255) / 256, 256>>>(w2, hw2, (int)(4 * MB1 / 4));

    dim3 gD(D_ / 128, NT / 128);    // (8, 64)
    dim3 gF(FF_ / 128, NT / 128);   // (32, 64)

    ln_k<<<NT, 256>>>(x, ln1g, ln1b, h);
    hgemm<false, false, true ><<<gD, 256>>>(h, hwq, bq, nullptr, nullptr, qb, NT, D_, D_);
    hgemm<false, false, true ><<<gD, 256>>>(h, hwk, bk, nullptr, nullptr, kb, NT, D_, D_);
    hgemm<false, false, true ><<<gD, 256>>>(h, hwv, bv, nullptr, nullptr, vb, NT, D_, D_);
    flash_h<<<dim3(T_ / 128, B_ * H_), 128, flash_smem>>>(qb, kb, vb, att);
    hgemm<false, true,  false><<<gD, 256>>>(att, hwo, bo, x, x2, nullptr, NT, D_, D_);
    ln_k<<<NT, 256>>>(x2, ln2g, ln2b, h);
    hgemm<true,  false, true ><<<gF, 256>>>(h, hw1, b1, nullptr, nullptr, ff, NT, FF_, D_);
    hgemm<false, true,  false><<<gD, 256>>>(ff, hw2, b2, x2, out, nullptr, NT, D_, FF_);
}

// round 7
// speedup vs baseline: 1.9726x; 1.1767x over previous
#include <cuda_runtime.h>
#include <cuda_fp16.h>
#include <math.h>
#include <stdint.h>

#define B_  4
#define T_  2048
#define D_  1024
#define H_  16
#define DH_ 64
#define FF_ 4096
#define NT  (B_*T_)   // 8192

// ---------------- scratch ----------------
__device__ __half g_hh [(size_t)NT*D_];
__device__ __half g_qh [(size_t)NT*D_];
__device__ __half g_kh [(size_t)NT*D_];
__device__ __half g_vh [(size_t)NT*D_];
__device__ __half g_ah [(size_t)NT*D_];
__device__ __half g_fh [(size_t)NT*FF_];
__device__ float  g_x2 [(size_t)NT*D_];
__device__ __half g_wh [(size_t)12*1024*1024];

// ---------------- weight fp32 -> fp16 ----------------
__global__ void __launch_bounds__(256) w2h_k(const float* __restrict__ src,
                                             __half* __restrict__ dst, int n4)
{
    int i = blockIdx.x * 256 + threadIdx.x;
    if (i < n4) {
        float4 v = ((const float4*)src)[i];
        *(half2*)(dst + (size_t)i * 4)     = __floats2half2_rn(v.x, v.y);
        *(half2*)(dst + (size_t)i * 4 + 2) = __floats2half2_rn(v.z, v.w);
    }
}

// ---------------- LayerNorm: fp32 in, fp16 out ----------------
__global__ void __launch_bounds__(256) ln_k(const float* __restrict__ x,
                                            const float* __restrict__ g,
                                            const float* __restrict__ b,
                                            __half* __restrict__ out)
{
    __shared__ float red[2][8];
    int row = blockIdx.x;
    int tid = threadIdx.x;
    const float* xr = x + (size_t)row * D_;
    int c = tid * 4;
    float4 xv = *(const float4*)(xr + c);
    float s  = xv.x + xv.y + xv.z + xv.w;
    float ss = xv.x*xv.x + xv.y*xv.y + xv.z*xv.z + xv.w*xv.w;
    #pragma unroll
    for (int o = 16; o > 0; o >>= 1) {
        s  += __shfl_down_sync(0xffffffffu, s,  o);
        ss += __shfl_down_sync(0xffffffffu, ss, o);
    }
    if ((tid & 31) == 0) { red[0][tid >> 5] = s; red[1][tid >> 5] = ss; }
    __syncthreads();
    if (tid < 32) {
        s  = (tid < 8) ? red[0][tid] : 0.f;
        ss = (tid < 8) ? red[1][tid] : 0.f;
        #pragma unroll
        for (int o = 4; o > 0; o >>= 1) {
            s  += __shfl_down_sync(0xffffffffu, s,  o);
            ss += __shfl_down_sync(0xffffffffu, ss, o);
        }
        if (tid == 0) { red[0][0] = s; red[1][0] = ss; }
    }
    __syncthreads();
    float mean = red[0][0] * (1.f / D_);
    float var  = red[1][0] * (1.f / D_) - mean * mean;
    float rstd = rsqrtf(var + 1e-5f);
    float4 gv = *(const float4*)(g + c);
    float4 bv = *(const float4*)(b + c);
    float o0 = (xv.x - mean) * rstd * gv.x + bv.x;
    float o1 = (xv.y - mean) * rstd * gv.y + bv.y;
    float o2 = (xv.z - mean) * rstd * gv.z + bv.z;
    float o3 = (xv.w - mean) * rstd * gv.w + bv.w;
    *(half2*)(out + (size_t)row * D_ + c)     = __floats2half2_rn(o0, o1);
    *(half2*)(out + (size_t)row * D_ + c + 2) = __floats2half2_rn(o2, o3);
}

// ---------------- mma / ldmatrix / cp.async helpers ----------------
__device__ __forceinline__ void mma_f16(float4& c,
                                        unsigned a0, unsigned a1, unsigned a2, unsigned a3,
                                        unsigned b0, unsigned b1)
{
    asm volatile("mma.sync.aligned.m16n8k16.row.col.f32.f16.f16.f32 "
                 "{%0,%1,%2,%3}, {%4,%5,%6,%7}, {%8,%9}, {%0,%1,%2,%3};"
                 : "+f"(c.x), "+f"(c.y), "+f"(c.z), "+f"(c.w)
                 : "r"(a0), "r"(a1), "r"(a2), "r"(a3), "r"(b0), "r"(b1));
}
__device__ __forceinline__ void ldsm4(unsigned& r0, unsigned& r1, unsigned& r2, unsigned& r3,
                                      const __half* p)
{
    uint32_t a = (uint32_t)__cvta_generic_to_shared(p);
    asm volatile("ldmatrix.sync.aligned.m8n8.x4.shared.b16 {%0,%1,%2,%3}, [%4];"
                 : "=r"(r0), "=r"(r1), "=r"(r2), "=r"(r3) : "r"(a));
}
__device__ __forceinline__ void ldsm4t(unsigned& r0, unsigned& r1, unsigned& r2, unsigned& r3,
                                       const __half* p)
{
    uint32_t a = (uint32_t)__cvta_generic_to_shared(p);
    asm volatile("ldmatrix.sync.aligned.m8n8.x4.trans.shared.b16 {%0,%1,%2,%3}, [%4];"
                 : "=r"(r0), "=r"(r1), "=r"(r2), "=r"(r3) : "r"(a));
}
__device__ __forceinline__ void cp16(const __half* smem_dst, const __half* gptr) {
    uint32_t a = (uint32_t)__cvta_generic_to_shared(smem_dst);
    asm volatile("cp.async.cg.shared.global [%0], [%1], 16;\n" :: "r"(a), "l"(gptr));
}
__device__ __forceinline__ void cp_commit() { asm volatile("cp.async.commit_group;\n"); }
template<int N>
__device__ __forceinline__ void cp_wait() { asm volatile("cp.async.wait_group %0;\n" :: "n"(N)); }

// ---------------- fp16 GEMM: C[M,N] = A[M,K] @ W[N,K]^T + bias (+res)(gelu) ------
// 128x128 tile, BK=32, 256 threads (8 warps 2x4), warp tile 64x32.
// 2-stage cp.async pipeline, ldmatrix fragment loads.
#define SPADH 40
template<bool GELU, bool RES, bool HOUT>
__global__ void __launch_bounds__(256) hgemm(const __half* __restrict__ A,
                                             const __half* __restrict__ W,
                                             const float* __restrict__ bias,
                                             const float* __restrict__ res,
                                             float* __restrict__ Cf,
                                             __half* __restrict__ Ch,
                                             int M, int N, int K)
{
    __shared__ __half As[2][128 * SPADH];
    __shared__ __half Bs[2][128 * SPADH];

    int tid  = threadIdx.x;
    int warp = tid >> 5;
    int lane = tid & 31;
    int g = lane >> 2;
    int t = lane & 3;
    int wm = (warp >> 2) * 64;
    int wn = (warp & 3) * 32;

    int m0 = blockIdx.y * 128;
    int n0 = blockIdx.x * 128;

    // cp.async coords: 512 chunks of 8 halves per matrix, 2 per thread
    int lrow[2], lcb[2];
    #pragma unroll
    for (int u = 0; u < 2; u++) {
        int lin = tid + u * 256;
        lrow[u] = lin >> 2;
        lcb[u]  = (lin & 3) * 8;
    }

    // ldmatrix lane offsets
    int arow = (lane & 15);
    int acol = 8 * (lane >> 4);
    int brow = (lane & 7) + ((lane >> 4) << 3);
    int bcol = 8 * ((lane >> 3) & 1);

    float4 acc[4][4];
    #pragma unroll
    for (int i = 0; i < 4; i++)
        #pragma unroll
        for (int j = 0; j < 4; j++) acc[i][j] = make_float4(0.f, 0.f, 0.f, 0.f);

    // prologue: stages 0,1
    #pragma unroll
    for (int st = 0; st < 2; st++) {
        #pragma unroll
        for (int u = 0; u < 2; u++) {
            cp16(&As[st][lrow[u] * SPADH + lcb[u]],
                 A + (size_t)(m0 + lrow[u]) * K + st * 32 + lcb[u]);
            cp16(&Bs[st][lrow[u] * SPADH + lcb[u]],
                 W + (size_t)(n0 + lrow[u]) * K + st * 32 + lcb[u]);
        }
        cp_commit();
    }

    int niter = K >> 5;
    for (int kt = 0; kt < niter; kt++) {
        cp_wait<1>();
        __syncthreads();
        int buf = kt & 1;
        const __half* Ab = As[buf];
        const __half* Bb = Bs[buf];

        #pragma unroll
        for (int kk = 0; kk < 32; kk += 16) {
            unsigned af[4][4];
            #pragma unroll
            for (int i = 0; i < 4; i++)
                ldsm4(af[i][0], af[i][1], af[i][2], af[i][3],
                      &Ab[(wm + 16 * i + arow) * SPADH + kk + acol]);
            unsigned bf[4][2];
            #pragma unroll
            for (int jj = 0; jj < 2; jj++)
                ldsm4(bf[2 * jj][0], bf[2 * jj][1], bf[2 * jj + 1][0], bf[2 * jj + 1][1],
                      &Bb[(wn + 16 * jj + brow) * SPADH + kk + bcol]);
            #pragma unroll
            for (int i = 0; i < 4; i++)
                #pragma unroll
                for (int j = 0; j < 4; j++)
                    mma_f16(acc[i][j], af[i][0], af[i][1], af[i][2], af[i][3],
                            bf[j][0], bf[j][1]);
        }
        __syncthreads();
        if (kt + 2 < niter) {
            int k0n = (kt + 2) * 32;
            #pragma unroll
            for (int u = 0; u < 2; u++) {
                cp16(&As[buf][lrow[u] * SPADH + lcb[u]],
                     A + (size_t)(m0 + lrow[u]) * K + k0n + lcb[u]);
                cp16(&Bs[buf][lrow[u] * SPADH + lcb[u]],
                     W + (size_t)(n0 + lrow[u]) * K + k0n + lcb[u]);
            }
        }
        cp_commit();
    }

    #pragma unroll
    for (int i = 0; i < 4; i++) {
        int r0 = m0 + wm + 16 * i + g;
        int r1 = r0 + 8;
        #pragma unroll
        for (int j = 0; j < 4; j++) {
            int col = n0 + wn + 8 * j + 2 * t;
            float b0 = bias[col], b1 = bias[col + 1];
            float v0 = acc[i][j].x + b0;
            float v1 = acc[i][j].y + b1;
            float v2 = acc[i][j].z + b0;
            float v3 = acc[i][j].w + b1;
            if (RES) {
                const float* rp0 = res + (size_t)r0 * N + col;
                const float* rp1 = res + (size_t)r1 * N + col;
                v0 += rp0[0]; v1 += rp0[1]; v2 += rp1[0]; v3 += rp1[1];
            }
            if (GELU) {
                v0 *= normcdff(v0); v1 *= normcdff(v1);
                v2 *= normcdff(v2); v3 *= normcdff(v3);
            }
            if (HOUT) {
                *(half2*)(Ch + (size_t)r0 * N + col) = __floats2half2_rn(v0, v1);
                *(half2*)(Ch + (size_t)r1 * N + col) = __floats2half2_rn(v2, v3);
            } else {
                *(float2*)(Cf + (size_t)r0 * N + col) = make_float2(v0, v1);
                *(float2*)(Cf + (size_t)r1 * N + col) = make_float2(v2, v3);
            }
        }
    }
}

// ---------------- fp16 flash attention (ldmatrix everywhere) ----------------
// 128 queries/CTA, 4 warps x 32 rows, 64-key tiles, fp32 online softmax.
// Q fragments hoisted to registers; V stored row-major, loaded via ldmatrix.trans.
#define FSP 72
__global__ void __launch_bounds__(128) flash_h(const __half* __restrict__ q,
                                               const __half* __restrict__ k,
                                               const __half* __restrict__ v,
                                               __half* __restrict__ o)
{
    extern __shared__ __half smh[];
    __half* Qs = smh;                  // [128][FSP]
    __half* Ks = Qs + 128 * FSP;       // [64][FSP]   (key-major)
    __half* Vs = Ks + 64 * FSP;        // [64][FSP]   (key-major!)
    __half* Ps = Vs + 64 * FSP;        // [128][FSP]

    int tid  = threadIdx.x;
    int warp = tid >> 5;
    int lane = tid & 31;
    int g = lane >> 2;
    int t = lane & 3;

    int bh = blockIdx.y;
    int b  = bh >> 4;
    int h  = bh & 15;
    int qt0 = blockIdx.x * 128;
    size_t base = ((size_t)b * T_) * D_ + (size_t)h * DH_;

    // ldmatrix lane offsets
    int arow = (lane & 15);
    int acol = 8 * (lane >> 4);
    int brow = (lane & 7) + ((lane >> 4) << 3);
    int bcol = 8 * ((lane >> 3) & 1);
    int vrow = (lane & 7) + (((lane >> 3) & 1) << 3);
    int vcol = 8 * (lane >> 4);

    // Q tile (scaled by 1/8)
    {
        half2 sc = __float2half2_rn(0.125f);
        #pragma unroll
        for (int it = 0; it < 8; it++) {
            int lin = tid + it * 128;
            int row = lin >> 3;
            int cb  = (lin & 7) * 8;
            uint4 u = *(const uint4*)(q + base + (size_t)(qt0 + row) * D_ + cb);
            half2* hp = (half2*)&u;
            hp[0] = __hmul2(hp[0], sc); hp[1] = __hmul2(hp[1], sc);
            hp[2] = __hmul2(hp[2], sc); hp[3] = __hmul2(hp[3], sc);
            *(uint4*)&Qs[row * FSP + cb] = u;
        }
    }
    __syncthreads();

    int r0w = warp * 32;

    // hoist Q fragments (loop-invariant)
    unsigned qf[2][4][4];
    #pragma unroll
    for (int mb = 0; mb < 2; mb++)
        #pragma unroll
        for (int ks = 0; ks < 4; ks++)
            ldsm4(qf[mb][ks][0], qf[mb][ks][1], qf[mb][ks][2], qf[mb][ks][3],
                  &Qs[(r0w + 16 * mb + arow) * FSP + ks * 16 + acol]);

    float m_i[4] = {-1e30f, -1e30f, -1e30f, -1e30f};
    float l_i[4] = {0.f, 0.f, 0.f, 0.f};
    float4 oacc[2][8];
    #pragma unroll
    for (int mb = 0; mb < 2; mb++)
        #pragma unroll
        for (int nb = 0; nb < 8; nb++) oacc[mb][nb] = make_float4(0.f, 0.f, 0.f, 0.f);

    for (int kt0 = 0; kt0 < T_; kt0 += 64) {
        __syncthreads();
        // K and V tiles, both key-major, vectorized
        #pragma unroll
        for (int it = 0; it < 4; it++) {
            int lin = tid + it * 128;
            int row = lin >> 3;
            int cb  = (lin & 7) * 8;
            *(uint4*)&Ks[row * FSP + cb] =
                *(const uint4*)(k + base + (size_t)(kt0 + row) * D_ + cb);
            *(uint4*)&Vs[row * FSP + cb] =
                *(const uint4*)(v + base + (size_t)(kt0 + row) * D_ + cb);
        }
        __syncthreads();

        // S = Q @ K^T (32x64 per warp)
        float4 sacc[2][8];
        #pragma unroll
        for (int mb = 0; mb < 2; mb++)
            #pragma unroll
            for (int nb = 0; nb < 8; nb++) sacc[mb][nb] = make_float4(0.f, 0.f, 0.f, 0.f);
        #pragma unroll
        for (int ks = 0; ks < 4; ks++) {
            unsigned bb[8][2];
            #pragma unroll
            for (int jj = 0; jj < 4; jj++)
                ldsm4(bb[2 * jj][0], bb[2 * jj][1], bb[2 * jj + 1][0], bb[2 * jj + 1][1],
                      &Ks[(16 * jj + brow) * FSP + ks * 16 + bcol]);
            #pragma unroll
            for (int mb = 0; mb < 2; mb++)
                #pragma unroll
                for (int nb = 0; nb < 8; nb++)
                    mma_f16(sacc[mb][nb], qf[mb][ks][0], qf[mb][ks][1],
                            qf[mb][ks][2], qf[mb][ks][3], bb[nb][0], bb[nb][1]);
        }

        // online softmax; write P (half) to Ps
        #pragma unroll
        for (int mb = 0; mb < 2; mb++) {
            float mx0 = -1e30f, mx1 = -1e30f;
            #pragma unroll
            for (int nb = 0; nb < 8; nb++) {
                mx0 = fmaxf(mx0, fmaxf(sacc[mb][nb].x, sacc[mb][nb].y));
                mx1 = fmaxf(mx1, fmaxf(sacc[mb][nb].z, sacc[mb][nb].w));
            }
            mx0 = fmaxf(mx0, __shfl_xor_sync(0xffffffffu, mx0, 1));
            mx0 = fmaxf(mx0, __shfl_xor_sync(0xffffffffu, mx0, 2));
            mx1 = fmaxf(mx1, __shfl_xor_sync(0xffffffffu, mx1, 1));
            mx1 = fmaxf(mx1, __shfl_xor_sync(0xffffffffu, mx1, 2));

            float mn0 = fmaxf(m_i[2 * mb + 0], mx0);
            float mn1 = fmaxf(m_i[2 * mb + 1], mx1);
            float al0 = __expf(m_i[2 * mb + 0] - mn0);
            float al1 = __expf(m_i[2 * mb + 1] - mn1);
            m_i[2 * mb + 0] = mn0;
            m_i[2 * mb + 1] = mn1;

            float s0 = 0.f, s1 = 0.f;
            int rbase  = (r0w + mb * 16 + g) * FSP;
            int rbase8 = (r0w + mb * 16 + g + 8) * FSP;
            #pragma unroll
            for (int nb = 0; nb < 8; nb++) {
                float p0 = __expf(sacc[mb][nb].x - mn0);
                float p1 = __expf(sacc[mb][nb].y - mn0);
                float p2 = __expf(sacc[mb][nb].z - mn1);
                float p3 = __expf(sacc[mb][nb].w - mn1);
                s0 += p0 + p1; s1 += p2 + p3;
                int cc = nb * 8 + 2 * t;
                *(half2*)&Ps[rbase + cc]  = __floats2half2_rn(p0, p1);
                *(half2*)&Ps[rbase8 + cc] = __floats2half2_rn(p2, p3);
            }
            s0 += __shfl_xor_sync(0xffffffffu, s0, 1);
            s0 += __shfl_xor_sync(0xffffffffu, s0, 2);
            s1 += __shfl_xor_sync(0xffffffffu, s1, 1);
            s1 += __shfl_xor_sync(0xffffffffu, s1, 2);
            l_i[2 * mb + 0] = l_i[2 * mb + 0] * al0 + s0;
            l_i[2 * mb + 1] = l_i[2 * mb + 1] * al1 + s1;

            #pragma unroll
            for (int nb = 0; nb < 8; nb++) {
                oacc[mb][nb].x *= al0; oacc[mb][nb].y *= al0;
                oacc[mb][nb].z *= al1; oacc[mb][nb].w *= al1;
            }
        }
        __syncwarp();

        // O += P @ V  (V fragments via ldmatrix.trans from key-major Vs)
        #pragma unroll
        for (int ks = 0; ks < 4; ks++) {
            unsigned pf[2][4];
            #pragma unroll
            for (int mb = 0; mb < 2; mb++)
                ldsm4(pf[mb][0], pf[mb][1], pf[mb][2], pf[mb][3],
                      &Ps[(r0w + 16 * mb + arow) * FSP + ks * 16 + acol]);
            unsigned vf[8][2];
            #pragma unroll
            for (int jj = 0; jj < 4; jj++)
                ldsm4t(vf[2 * jj][0], vf[2 * jj][1], vf[2 * jj + 1][0], vf[2 * jj + 1][1],
                       &Vs[(ks * 16 + vrow) * FSP + 16 * jj + vcol]);
            #pragma unroll
            for (int mb = 0; mb < 2; mb++)
                #pragma unroll
                for (int nb = 0; nb < 8; nb++)
                    mma_f16(oacc[mb][nb], pf[mb][0], pf[mb][1], pf[mb][2], pf[mb][3],
                            vf[nb][0], vf[nb][1]);
        }
    }

    // epilogue
    #pragma unroll
    for (int mb = 0; mb < 2; mb++) {
        float inv0 = 1.f / l_i[2 * mb + 0];
        float inv1 = 1.f / l_i[2 * mb + 1];
        int row0 = qt0 + r0w + mb * 16 + g;
        int row1 = row0 + 8;
        #pragma unroll
        for (int nb = 0; nb < 8; nb++) {
            int cc = nb * 8 + 2 * t;
            *(half2*)(o + base + (size_t)row0 * D_ + cc) =
                __floats2half2_rn(oacc[mb][nb].x * inv0, oacc[mb][nb].y * inv0);
            *(half2*)(o + base + (size_t)row1 * D_ + cc) =
                __floats2half2_rn(oacc[mb][nb].z * inv1, oacc[mb][nb].w * inv1);
        }
    }
}

// ---------------- launch ----------------
extern "C" void kernel_launch(void* const* d_in, const int* in_sizes, int n_in,
                              void* d_out, int out_size)
{
    const float* x    = (const float*)d_in[0];
    const float* ln1g = (const float*)d_in[1];
    const float* ln1b = (const float*)d_in[2];
    const float* ln2g = (const float*)d_in[3];
    const float* ln2b = (const float*)d_in[4];
    const float* wq   = (const float*)d_in[5];
    const float* bq   = (const float*)d_in[6];
    const float* wk   = (const float*)d_in[7];
    const float* bk   = (const float*)d_in[8];
    const float* wv   = (const float*)d_in[9];
    const float* bv   = (const float*)d_in[10];
    const float* wo   = (const float*)d_in[11];
    const float* bo   = (const float*)d_in[12];
    const float* w1   = (const float*)d_in[13];
    const float* b1   = (const float*)d_in[14];
    const float* w2   = (const float*)d_in[15];
    const float* b2   = (const float*)d_in[16];
    float* out = (float*)d_out;

    void* p;
    cudaGetSymbolAddress(&p, g_hh); __half* h   = (__half*)p;
    cudaGetSymbolAddress(&p, g_qh); __half* qb  = (__half*)p;
    cudaGetSymbolAddress(&p, g_kh); __half* kb  = (__half*)p;
    cudaGetSymbolAddress(&p, g_vh); __half* vb  = (__half*)p;
    cudaGetSymbolAddress(&p, g_ah); __half* att = (__half*)p;
    cudaGetSymbolAddress(&p, g_fh); __half* ff  = (__half*)p;
    cudaGetSymbolAddress(&p, g_x2); float*  x2  = (float*)p;
    cudaGetSymbolAddress(&p, g_wh); __half* wh  = (__half*)p;

    const size_t MB1 = 1024 * 1024;
    __half* hwq = wh;
    __half* hwk = wh + 1 * MB1;
    __half* hwv = wh + 2 * MB1;
    __half* hwo = wh + 3 * MB1;
    __half* hw1 = wh + 4 * MB1;
    __half* hw2 = wh + 8 * MB1;

    int flash_smem = (128 + 64 + 64 + 128) * FSP * (int)sizeof(__half);
    cudaFuncSetAttribute(flash_h, cudaFuncAttributeMaxDynamicSharedMemorySize, flash_smem);

    w2h_k<<<(int)(1 * MB1 / 4 + 255) / 256, 256>>>(wq, hwq, (int)(1 * MB1 / 4));
    w2h_k<<<(int)(1 * MB1 / 4 + 255) / 256, 256>>>(wk, hwk, (int)(1 * MB1 / 4));
    w2h_k<<<(int)(1 * MB1 / 4 + 255) / 256, 256>>>(wv, hwv, (int)(1 * MB1 / 4));
    w2h_k<<<(int)(1 * MB1 / 4 + 255) / 256, 256>>>(wo, hwo, (int)(1 * MB1 / 4));
    w2h_k<<<(int)(4 * MB1 / 4 + 255) / 256, 256>>>(w1, hw1, (int)(4 * MB1 / 4));
    w2h_k<<<(int)(4 * MB1 / 4 + 255) / 256, 256>>>(w2, hw2, (int)(4 * MB1 / 4));

    dim3 gD(D_ / 128, NT / 128);    // (8, 64)
    dim3 gF(FF_ / 128, NT / 128);   // (32, 64)

    ln_k<<<NT, 256>>>(x, ln1g, ln1b, h);
    hgemm<false, false, true ><<<gD, 256>>>(h, hwq, bq, nullptr, nullptr, qb, NT, D_, D_);
    hgemm<false, false, true ><<<gD, 256>>>(h, hwk, bk, nullptr, nullptr, kb, NT, D_, D_);
    hgemm<false, false, true ><<<gD, 256>>>(h, hwv, bv, nullptr, nullptr, vb, NT, D_, D_);
    flash_h<<<dim3(T_ / 128, B_ * H_), 128, flash_smem>>>(qb, kb, vb, att);
    hgemm<false, true,  false><<<gD, 256>>>(att, hwo, bo, x, x2, nullptr, NT, D_, D_);
    ln_k<<<NT, 256>>>(x2, ln2g, ln2b, h);
    hgemm<true,  false, true ><<<gF, 256>>>(h, hw1, b1, nullptr, nullptr, ff, NT, FF_, D_);
    hgemm<false, true,  false><<<gD, 256>>>(ff, hw2, b2, x2, out, nullptr, NT, D_, FF_);
}

// round 8
// speedup vs baseline: 2.0138x; 1.0209x over previous
#include <cuda_runtime.h>
#include <cuda_fp16.h>
#include <math.h>
#include <stdint.h>

#define B_  4
#define T_  2048
#define D_  1024
#define H_  16
#define DH_ 64
#define FF_ 4096
#define NT  (B_*T_)   // 8192
#define QKVN 3072

// ---------------- scratch ----------------
__device__ __half g_hh  [(size_t)NT*D_];
__device__ __half g_qkv [(size_t)NT*QKVN];
__device__ __half g_ah  [(size_t)NT*D_];
__device__ __half g_fh  [(size_t)NT*FF_];
__device__ float  g_x2  [(size_t)NT*D_];
__device__ __half g_wh  [(size_t)12*1024*1024];
__device__ float  g_bqkv[QKVN];

// ---------------- all-weights fp32 -> fp16 (one launch) ----------------
// dst layout (halves): [wqkv 3M][wo 1M][w1 4M][w2 4M]; total 12M halves = 3M float4
#define SEG (262144)   // 1M halves = 256K float4 chunks
__global__ void __launch_bounds__(256) w2h_all(const float* __restrict__ wq,
                                               const float* __restrict__ wk,
                                               const float* __restrict__ wv,
                                               const float* __restrict__ wo,
                                               const float* __restrict__ w1,
                                               const float* __restrict__ w2,
                                               __half* __restrict__ dst)
{
    int i = blockIdx.x * 256 + threadIdx.x;   // float4 chunk index, < 3M
    if (i >= 12 * SEG) return;
    const float* src;
    int s;
    if      (i <  1 * SEG) { src = wq; s = i; }
    else if (i <  2 * SEG) { src = wk; s = i - 1 * SEG; }
    else if (i <  3 * SEG) { src = wv; s = i - 2 * SEG; }
    else if (i <  4 * SEG) { src = wo; s = i - 3 * SEG; }
    else if (i <  8 * SEG) { src = w1; s = i - 4 * SEG; }
    else                   { src = w2; s = i - 8 * SEG; }
    float4 v = ((const float4*)src)[s];
    __half* d = dst + (size_t)i * 4;
    *(half2*)(d)     = __floats2half2_rn(v.x, v.y);
    *(half2*)(d + 2) = __floats2half2_rn(v.z, v.w);
}

__global__ void __launch_bounds__(256) bpack_k(const float* __restrict__ bq,
                                               const float* __restrict__ bk,
                                               const float* __restrict__ bv,
                                               float* __restrict__ dst)
{
    int i = blockIdx.x * 256 + threadIdx.x;
    if (i < D_) {
        dst[i] = bq[i];
        dst[i + D_] = bk[i];
        dst[i + 2 * D_] = bv[i];
    }
}

// ---------------- LayerNorm: fp32 in, fp16 out ----------------
__global__ void __launch_bounds__(256) ln_k(const float* __restrict__ x,
                                            const float* __restrict__ g,
                                            const float* __restrict__ b,
                                            __half* __restrict__ out)
{
    __shared__ float red[2][8];
    int row = blockIdx.x;
    int tid = threadIdx.x;
    const float* xr = x + (size_t)row * D_;
    int c = tid * 4;
    float4 xv = *(const float4*)(xr + c);
    float s  = xv.x + xv.y + xv.z + xv.w;
    float ss = xv.x*xv.x + xv.y*xv.y + xv.z*xv.z + xv.w*xv.w;
    #pragma unroll
    for (int o = 16; o > 0; o >>= 1) {
        s  += __shfl_down_sync(0xffffffffu, s,  o);
        ss += __shfl_down_sync(0xffffffffu, ss, o);
    }
    if ((tid & 31) == 0) { red[0][tid >> 5] = s; red[1][tid >> 5] = ss; }
    __syncthreads();
    if (tid < 32) {
        s  = (tid < 8) ? red[0][tid] : 0.f;
        ss = (tid < 8) ? red[1][tid] : 0.f;
        #pragma unroll
        for (int o = 4; o > 0; o >>= 1) {
            s  += __shfl_down_sync(0xffffffffu, s,  o);
            ss += __shfl_down_sync(0xffffffffu, ss, o);
        }
        if (tid == 0) { red[0][0] = s; red[1][0] = ss; }
    }
    __syncthreads();
    float mean = red[0][0] * (1.f / D_);
    float var  = red[1][0] * (1.f / D_) - mean * mean;
    float rstd = rsqrtf(var + 1e-5f);
    float4 gv = *(const float4*)(g + c);
    float4 bv = *(const float4*)(b + c);
    float o0 = (xv.x - mean) * rstd * gv.x + bv.x;
    float o1 = (xv.y - mean) * rstd * gv.y + bv.y;
    float o2 = (xv.z - mean) * rstd * gv.z + bv.z;
    float o3 = (xv.w - mean) * rstd * gv.w + bv.w;
    *(half2*)(out + (size_t)row * D_ + c)     = __floats2half2_rn(o0, o1);
    *(half2*)(out + (size_t)row * D_ + c + 2) = __floats2half2_rn(o2, o3);
}

// ---------------- mma / ldmatrix / cp.async helpers ----------------
__device__ __forceinline__ void mma_f16(float4& c,
                                        unsigned a0, unsigned a1, unsigned a2, unsigned a3,
                                        unsigned b0, unsigned b1)
{
    asm volatile("mma.sync.aligned.m16n8k16.row.col.f32.f16.f16.f32 "
                 "{%0,%1,%2,%3}, {%4,%5,%6,%7}, {%8,%9}, {%0,%1,%2,%3};"
                 : "+f"(c.x), "+f"(c.y), "+f"(c.z), "+f"(c.w)
                 : "r"(a0), "r"(a1), "r"(a2), "r"(a3), "r"(b0), "r"(b1));
}
__device__ __forceinline__ void ldsm4(unsigned& r0, unsigned& r1, unsigned& r2, unsigned& r3,
                                      const __half* p)
{
    uint32_t a = (uint32_t)__cvta_generic_to_shared(p);
    asm volatile("ldmatrix.sync.aligned.m8n8.x4.shared.b16 {%0,%1,%2,%3}, [%4];"
                 : "=r"(r0), "=r"(r1), "=r"(r2), "=r"(r3) : "r"(a));
}
__device__ __forceinline__ void ldsm4t(unsigned& r0, unsigned& r1, unsigned& r2, unsigned& r3,
                                       const __half* p)
{
    uint32_t a = (uint32_t)__cvta_generic_to_shared(p);
    asm volatile("ldmatrix.sync.aligned.m8n8.x4.trans.shared.b16 {%0,%1,%2,%3}, [%4];"
                 : "=r"(r0), "=r"(r1), "=r"(r2), "=r"(r3) : "r"(a));
}
__device__ __forceinline__ void cp16(const __half* smem_dst, const __half* gptr) {
    uint32_t a = (uint32_t)__cvta_generic_to_shared(smem_dst);
    asm volatile("cp.async.cg.shared.global [%0], [%1], 16;\n" :: "r"(a), "l"(gptr));
}
__device__ __forceinline__ void cp_commit() { asm volatile("cp.async.commit_group;\n"); }
template<int N>
__device__ __forceinline__ void cp_wait() { asm volatile("cp.async.wait_group %0;\n" :: "n"(N)); }

// ---------------- fp16 GEMM (R6-proven): C[M,N] = A[M,K] @ W[N,K]^T ----------------
#define SPADH 40
template<bool GELU, bool RES, bool HOUT>
__global__ void __launch_bounds__(256) hgemm(const __half* __restrict__ A,
                                             const __half* __restrict__ W,
                                             const float* __restrict__ bias,
                                             const float* __restrict__ res,
                                             float* __restrict__ Cf,
                                             __half* __restrict__ Ch,
                                             int M, int N, int K)
{
    __shared__ __half As[2][128 * SPADH];
    __shared__ __half Bs[2][128 * SPADH];

    int tid  = threadIdx.x;
    int warp = tid >> 5;
    int lane = tid & 31;
    int g = lane >> 2;
    int t = lane & 3;
    int wm = (warp >> 2) * 64;
    int wn = (warp & 3) * 32;

    int m0 = blockIdx.y * 128;
    int n0 = blockIdx.x * 128;

    int lrow[2], lcb[2];
    #pragma unroll
    for (int u = 0; u < 2; u++) {
        int lin = tid + u * 256;
        lrow[u] = lin >> 2;
        lcb[u]  = (lin & 3) * 8;
    }

    int arow = (lane & 15);
    int acol = 8 * (lane >> 4);
    int brow = (lane & 7) + ((lane >> 4) << 3);
    int bcol = 8 * ((lane >> 3) & 1);

    float4 acc[4][4];
    #pragma unroll
    for (int i = 0; i < 4; i++)
        #pragma unroll
        for (int j = 0; j < 4; j++) acc[i][j] = make_float4(0.f, 0.f, 0.f, 0.f);

    #pragma unroll
    for (int st = 0; st < 2; st++) {
        #pragma unroll
        for (int u = 0; u < 2; u++) {
            cp16(&As[st][lrow[u] * SPADH + lcb[u]],
                 A + (size_t)(m0 + lrow[u]) * K + st * 32 + lcb[u]);
            cp16(&Bs[st][lrow[u] * SPADH + lcb[u]],
                 W + (size_t)(n0 + lrow[u]) * K + st * 32 + lcb[u]);
        }
        cp_commit();
    }

    int niter = K >> 5;
    for (int kt = 0; kt < niter; kt++) {
        cp_wait<1>();
        __syncthreads();
        int buf = kt & 1;
        const __half* Ab = As[buf];
        const __half* Bb = Bs[buf];

        #pragma unroll
        for (int kk = 0; kk < 32; kk += 16) {
            unsigned af[4][4];
            #pragma unroll
            for (int i = 0; i < 4; i++)
                ldsm4(af[i][0], af[i][1], af[i][2], af[i][3],
                      &Ab[(wm + 16 * i + arow) * SPADH + kk + acol]);
            unsigned bf[4][2];
            #pragma unroll
            for (int jj = 0; jj < 2; jj++)
                ldsm4(bf[2 * jj][0], bf[2 * jj][1], bf[2 * jj + 1][0], bf[2 * jj + 1][1],
                      &Bb[(wn + 16 * jj + brow) * SPADH + kk + bcol]);
            #pragma unroll
            for (int i = 0; i < 4; i++)
                #pragma unroll
                for (int j = 0; j < 4; j++)
                    mma_f16(acc[i][j], af[i][0], af[i][1], af[i][2], af[i][3],
                            bf[j][0], bf[j][1]);
        }
        __syncthreads();
        if (kt + 2 < niter) {
            int k0n = (kt + 2) * 32;
            #pragma unroll
            for (int u = 0; u < 2; u++) {
                cp16(&As[buf][lrow[u] * SPADH + lcb[u]],
                     A + (size_t)(m0 + lrow[u]) * K + k0n + lcb[u]);
                cp16(&Bs[buf][lrow[u] * SPADH + lcb[u]],
                     W + (size_t)(n0 + lrow[u]) * K + k0n + lcb[u]);
            }
        }
        cp_commit();
    }

    #pragma unroll
    for (int i = 0; i < 4; i++) {
        int r0 = m0 + wm + 16 * i + g;
        int r1 = r0 + 8;
        #pragma unroll
        for (int j = 0; j < 4; j++) {
            int col = n0 + wn + 8 * j + 2 * t;
            float b0 = bias[col], b1 = bias[col + 1];
            float v0 = acc[i][j].x + b0;
            float v1 = acc[i][j].y + b1;
            float v2 = acc[i][j].z + b0;
            float v3 = acc[i][j].w + b1;
            if (RES) {
                const float* rp0 = res + (size_t)r0 * N + col;
                const float* rp1 = res + (size_t)r1 * N + col;
                v0 += rp0[0]; v1 += rp0[1]; v2 += rp1[0]; v3 += rp1[1];
            }
            if (GELU) {
                v0 *= normcdff(v0); v1 *= normcdff(v1);
                v2 *= normcdff(v2); v3 *= normcdff(v3);
            }
            if (HOUT) {
                *(half2*)(Ch + (size_t)r0 * N + col) = __floats2half2_rn(v0, v1);
                *(half2*)(Ch + (size_t)r1 * N + col) = __floats2half2_rn(v2, v3);
            } else {
                *(float2*)(Cf + (size_t)r0 * N + col) = make_float2(v0, v1);
                *(float2*)(Cf + (size_t)r1 * N + col) = make_float2(v2, v3);
            }
        }
    }
}

// ---------------- fp16 flash attention (reads packed qkv, stride 3072) ----------------
#define FSP 72
__global__ void __launch_bounds__(128) flash_h(const __half* __restrict__ qkv,
                                               __half* __restrict__ o)
{
    extern __shared__ __half smh[];
    __half* Qs = smh;
    __half* Ks = Qs + 128 * FSP;
    __half* Vs = Ks + 64 * FSP;
    __half* Ps = Vs + 64 * FSP;

    int tid  = threadIdx.x;
    int warp = tid >> 5;
    int lane = tid & 31;
    int g = lane >> 2;
    int t = lane & 3;

    int bh = blockIdx.y;
    int b  = bh >> 4;
    int h  = bh & 15;
    int qt0 = blockIdx.x * 128;
    size_t qbase = ((size_t)b * T_) * QKVN + (size_t)h * DH_;           // q cols
    size_t kbase = qbase + D_;                                          // k cols
    size_t vbase = qbase + 2 * D_;                                      // v cols
    size_t obase = ((size_t)b * T_) * D_ + (size_t)h * DH_;

    int arow = (lane & 15);
    int acol = 8 * (lane >> 4);
    int brow = (lane & 7) + ((lane >> 4) << 3);
    int bcol = 8 * ((lane >> 3) & 1);
    int vrow = (lane & 7) + (((lane >> 3) & 1) << 3);
    int vcol = 8 * (lane >> 4);

    {
        half2 sc = __float2half2_rn(0.125f);
        #pragma unroll
        for (int it = 0; it < 8; it++) {
            int lin = tid + it * 128;
            int row = lin >> 3;
            int cb  = (lin & 7) * 8;
            uint4 u = *(const uint4*)(qkv + qbase + (size_t)(qt0 + row) * QKVN + cb);
            half2* hp = (half2*)&u;
            hp[0] = __hmul2(hp[0], sc); hp[1] = __hmul2(hp[1], sc);
            hp[2] = __hmul2(hp[2], sc); hp[3] = __hmul2(hp[3], sc);
            *(uint4*)&Qs[row * FSP + cb] = u;
        }
    }
    __syncthreads();

    int r0w = warp * 32;

    unsigned qf[2][4][4];
    #pragma unroll
    for (int mb = 0; mb < 2; mb++)
        #pragma unroll
        for (int ks = 0; ks < 4; ks++)
            ldsm4(qf[mb][ks][0], qf[mb][ks][1], qf[mb][ks][2], qf[mb][ks][3],
                  &Qs[(r0w + 16 * mb + arow) * FSP + ks * 16 + acol]);

    float m_i[4] = {-1e30f, -1e30f, -1e30f, -1e30f};
    float l_i[4] = {0.f, 0.f, 0.f, 0.f};
    float4 oacc[2][8];
    #pragma unroll
    for (int mb = 0; mb < 2; mb++)
        #pragma unroll
        for (int nb = 0; nb < 8; nb++) oacc[mb][nb] = make_float4(0.f, 0.f, 0.f, 0.f);

    for (int kt0 = 0; kt0 < T_; kt0 += 64) {
        __syncthreads();
        #pragma unroll
        for (int it = 0; it < 4; it++) {
            int lin = tid + it * 128;
            int row = lin >> 3;
            int cb  = (lin & 7) * 8;
            *(uint4*)&Ks[row * FSP + cb] =
                *(const uint4*)(qkv + kbase + (size_t)(kt0 + row) * QKVN + cb);
            *(uint4*)&Vs[row * FSP + cb] =
                *(const uint4*)(qkv + vbase + (size_t)(kt0 + row) * QKVN + cb);
        }
        __syncthreads();

        float4 sacc[2][8];
        #pragma unroll
        for (int mb = 0; mb < 2; mb++)
            #pragma unroll
            for (int nb = 0; nb < 8; nb++) sacc[mb][nb] = make_float4(0.f, 0.f, 0.f, 0.f);
        #pragma unroll
        for (int ks = 0; ks < 4; ks++) {
            unsigned bb[8][2];
            #pragma unroll
            for (int jj = 0; jj < 4; jj++)
                ldsm4(bb[2 * jj][0], bb[2 * jj][1], bb[2 * jj + 1][0], bb[2 * jj + 1][1],
                      &Ks[(16 * jj + brow) * FSP + ks * 16 + bcol]);
            #pragma unroll
            for (int mb = 0; mb < 2; mb++)
                #pragma unroll
                for (int nb = 0; nb < 8; nb++)
                    mma_f16(sacc[mb][nb], qf[mb][ks][0], qf[mb][ks][1],
                            qf[mb][ks][2], qf[mb][ks][3], bb[nb][0], bb[nb][1]);
        }

        #pragma unroll
        for (int mb = 0; mb < 2; mb++) {
            float mx0 = -1e30f, mx1 = -1e30f;
            #pragma unroll
            for (int nb = 0; nb < 8; nb++) {
                mx0 = fmaxf(mx0, fmaxf(sacc[mb][nb].x, sacc[mb][nb].y));
                mx1 = fmaxf(mx1, fmaxf(sacc[mb][nb].z, sacc[mb][nb].w));
            }
            mx0 = fmaxf(mx0, __shfl_xor_sync(0xffffffffu, mx0, 1));
            mx0 = fmaxf(mx0, __shfl_xor_sync(0xffffffffu, mx0, 2));
            mx1 = fmaxf(mx1, __shfl_xor_sync(0xffffffffu, mx1, 1));
            mx1 = fmaxf(mx1, __shfl_xor_sync(0xffffffffu, mx1, 2));

            float mn0 = fmaxf(m_i[2 * mb + 0], mx0);
            float mn1 = fmaxf(m_i[2 * mb + 1], mx1);
            float al0 = __expf(m_i[2 * mb + 0] - mn0);
            float al1 = __expf(m_i[2 * mb + 1] - mn1);
            m_i[2 * mb + 0] = mn0;
            m_i[2 * mb + 1] = mn1;

            float s0 = 0.f, s1 = 0.f;
            int rbase  = (r0w + mb * 16 + g) * FSP;
            int rbase8 = (r0w + mb * 16 + g + 8) * FSP;
            #pragma unroll
            for (int nb = 0; nb < 8; nb++) {
                float p0 = __expf(sacc[mb][nb].x - mn0);
                float p1 = __expf(sacc[mb][nb].y - mn0);
                float p2 = __expf(sacc[mb][nb].z - mn1);
                float p3 = __expf(sacc[mb][nb].w - mn1);
                s0 += p0 + p1; s1 += p2 + p3;
                int cc = nb * 8 + 2 * t;
                *(half2*)&Ps[rbase + cc]  = __floats2half2_rn(p0, p1);
                *(half2*)&Ps[rbase8 + cc] = __floats2half2_rn(p2, p3);
            }
            s0 += __shfl_xor_sync(0xffffffffu, s0, 1);
            s0 += __shfl_xor_sync(0xffffffffu, s0, 2);
            s1 += __shfl_xor_sync(0xffffffffu, s1, 1);
            s1 += __shfl_xor_sync(0xffffffffu, s1, 2);
            l_i[2 * mb + 0] = l_i[2 * mb + 0] * al0 + s0;
            l_i[2 * mb + 1] = l_i[2 * mb + 1] * al1 + s1;

            #pragma unroll
            for (int nb = 0; nb < 8; nb++) {
                oacc[mb][nb].x *= al0; oacc[mb][nb].y *= al0;
                oacc[mb][nb].z *= al1; oacc[mb][nb].w *= al1;
            }
        }
        __syncwarp();

        #pragma unroll
        for (int ks = 0; ks < 4; ks++) {
            unsigned pf[2][4];
            #pragma unroll
            for (int mb = 0; mb < 2; mb++)
                ldsm4(pf[mb][0], pf[mb][1], pf[mb][2], pf[mb][3],
                      &Ps[(r0w + 16 * mb + arow) * FSP + ks * 16 + acol]);
            unsigned vf[8][2];
            #pragma unroll
            for (int jj = 0; jj < 4; jj++)
                ldsm4t(vf[2 * jj][0], vf[2 * jj][1], vf[2 * jj + 1][0], vf[2 * jj + 1][1],
                       &Vs[(ks * 16 + vrow) * FSP + 16 * jj + vcol]);
            #pragma unroll
            for (int mb = 0; mb < 2; mb++)
                #pragma unroll
                for (int nb = 0; nb < 8; nb++)
                    mma_f16(oacc[mb][nb], pf[mb][0], pf[mb][1], pf[mb][2], pf[mb][3],
                            vf[nb][0], vf[nb][1]);
        }
    }

    #pragma unroll
    for (int mb = 0; mb < 2; mb++) {
        float inv0 = 1.f / l_i[2 * mb + 0];
        float inv1 = 1.f / l_i[2 * mb + 1];
        int row0 = qt0 + r0w + mb * 16 + g;
        int row1 = row0 + 8;
        #pragma unroll
        for (int nb = 0; nb < 8; nb++) {
            int cc = nb * 8 + 2 * t;
            *(half2*)(o + obase + (size_t)row0 * D_ + cc) =
                __floats2half2_rn(oacc[mb][nb].x * inv0, oacc[mb][nb].y * inv0);
            *(half2*)(o + obase + (size_t)row1 * D_ + cc) =
                __floats2half2_rn(oacc[mb][nb].z * inv1, oacc[mb][nb].w * inv1);
        }
    }
}

// ---------------- launch ----------------
extern "C" void kernel_launch(void* const* d_in, const int* in_sizes, int n_in,
                              void* d_out, int out_size)
{
    const float* x    = (const float*)d_in[0];
    const float* ln1g = (const float*)d_in[1];
    const float* ln1b = (const float*)d_in[2];
    const float* ln2g = (const float*)d_in[3];
    const float* ln2b = (const float*)d_in[4];
    const float* wq   = (const float*)d_in[5];
    const float* bq   = (const float*)d_in[6];
    const float* wk   = (const float*)d_in[7];
    const float* bk   = (const float*)d_in[8];
    const float* wv   = (const float*)d_in[9];
    const float* bv   = (const float*)d_in[10];
    const float* wo   = (const float*)d_in[11];
    const float* bo   = (const float*)d_in[12];
    const float* w1   = (const float*)d_in[13];
    const float* b1   = (const float*)d_in[14];
    const float* w2   = (const float*)d_in[15];
    const float* b2   = (const float*)d_in[16];
    float* out = (float*)d_out;

    void* p;
    cudaGetSymbolAddress(&p, g_hh);   __half* h    = (__half*)p;
    cudaGetSymbolAddress(&p, g_qkv);  __half* qkv  = (__half*)p;
    cudaGetSymbolAddress(&p, g_ah);   __half* att  = (__half*)p;
    cudaGetSymbolAddress(&p, g_fh);   __half* ff   = (__half*)p;
    cudaGetSymbolAddress(&p, g_x2);   float*  x2   = (float*)p;
    cudaGetSymbolAddress(&p, g_wh);   __half* wh   = (__half*)p;
    cudaGetSymbolAddress(&p, g_bqkv); float*  bqkv = (float*)p;

    const size_t MB1 = 1024 * 1024;
    __half* hwqkv = wh;              // 3M halves  (N=3072, K=1024)
    __half* hwo   = wh + 3 * MB1;    // 1M
    __half* hw1   = wh + 4 * MB1;    // 4M
    __half* hw2   = wh + 8 * MB1;    // 4M

    int flash_smem = (128 + 64 + 64 + 128) * FSP * (int)sizeof(__half);
    cudaFuncSetAttribute(flash_h, cudaFuncAttributeMaxDynamicSharedMemorySize, flash_smem);

    // one conversion launch for all weights + bias pack
    w2h_all<<<(12 * SEG + 255) / 256, 256>>>(wq, wk, wv, wo, w1, w2, wh);
    bpack_k<<<(D_ + 255) / 256, 256>>>(bq, bk, bv, bqkv);

    dim3 gQKV(QKVN / 128, NT / 128);   // (24, 64)
    dim3 gD(D_ / 128, NT / 128);       // (8, 64)
    dim3 gF(FF_ / 128, NT / 128);      // (32, 64)

    ln_k<<<NT, 256>>>(x, ln1g, ln1b, h);
    hgemm<false, false, true ><<<gQKV, 256>>>(h, hwqkv, bqkv, nullptr, nullptr, qkv, NT, QKVN, D_);
    flash_h<<<dim3(T_ / 128, B_ * H_), 128, flash_smem>>>(qkv, att);
    hgemm<false, true,  false><<<gD, 256>>>(att, hwo, bo, x, x2, nullptr, NT, D_, D_);
    ln_k<<<NT, 256>>>(x2, ln2g, ln2b, h);
    hgemm<true,  false, true ><<<gF, 256>>>(h, hw1, b1, nullptr, nullptr, ff, NT, FF_, D_);
    hgemm<false, true,  false><<<gD, 256>>>(ff, hw2, b2, x2, out, nullptr, NT, D_, FF_);
}

// round 9
// speedup vs baseline: 2.1827x; 1.0839x over previous
#include <cuda_runtime.h>
#include <cuda_fp16.h>
#include <math.h>
#include <stdint.h>

#define B_  4
#define T_  2048
#define D_  1024
#define H_  16
#define DH_ 64
#define FF_ 4096
#define NT  (B_*T_)   // 8192
#define QKVN 3072

// ---------------- scratch ----------------
__device__ __half g_hh  [(size_t)NT*D_];
__device__ __half g_qkv [(size_t)NT*QKVN];
__device__ __half g_ah  [(size_t)NT*D_];
__device__ __half g_fh  [(size_t)NT*FF_];
__device__ float  g_x2  [(size_t)NT*D_];
__device__ __half g_wh  [(size_t)12*1024*1024];
__device__ float  g_bqkv[QKVN];

// ---------------- all-weights fp32 -> fp16 (one launch) ----------------
#define SEG (262144)
__global__ void __launch_bounds__(256) w2h_all(const float* __restrict__ wq,
                                               const float* __restrict__ wk,
                                               const float* __restrict__ wv,
                                               const float* __restrict__ wo,
                                               const float* __restrict__ w1,
                                               const float* __restrict__ w2,
                                               __half* __restrict__ dst)
{
    int i = blockIdx.x * 256 + threadIdx.x;
    if (i >= 12 * SEG) return;
    const float* src;
    int s;
    if      (i <  1 * SEG) { src = wq; s = i; }
    else if (i <  2 * SEG) { src = wk; s = i - 1 * SEG; }
    else if (i <  3 * SEG) { src = wv; s = i - 2 * SEG; }
    else if (i <  4 * SEG) { src = wo; s = i - 3 * SEG; }
    else if (i <  8 * SEG) { src = w1; s = i - 4 * SEG; }
    else                   { src = w2; s = i - 8 * SEG; }
    float4 v = ((const float4*)src)[s];
    __half* d = dst + (size_t)i * 4;
    *(half2*)(d)     = __floats2half2_rn(v.x, v.y);
    *(half2*)(d + 2) = __floats2half2_rn(v.z, v.w);
}

__global__ void __launch_bounds__(256) bpack_k(const float* __restrict__ bq,
                                               const float* __restrict__ bk,
                                               const float* __restrict__ bv,
                                               float* __restrict__ dst)
{
    int i = blockIdx.x * 256 + threadIdx.x;
    if (i < D_) {
        dst[i] = bq[i];
        dst[i + D_] = bk[i];
        dst[i + 2 * D_] = bv[i];
    }
}

// ---------------- LayerNorm: fp32 in, fp16 out ----------------
__global__ void __launch_bounds__(256) ln_k(const float* __restrict__ x,
                                            const float* __restrict__ g,
                                            const float* __restrict__ b,
                                            __half* __restrict__ out)
{
    __shared__ float red[2][8];
    int row = blockIdx.x;
    int tid = threadIdx.x;
    const float* xr = x + (size_t)row * D_;
    int c = tid * 4;
    float4 xv = *(const float4*)(xr + c);
    float s  = xv.x + xv.y + xv.z + xv.w;
    float ss = xv.x*xv.x + xv.y*xv.y + xv.z*xv.z + xv.w*xv.w;
    #pragma unroll
    for (int o = 16; o > 0; o >>= 1) {
        s  += __shfl_down_sync(0xffffffffu, s,  o);
        ss += __shfl_down_sync(0xffffffffu, ss, o);
    }
    if ((tid & 31) == 0) { red[0][tid >> 5] = s; red[1][tid >> 5] = ss; }
    __syncthreads();
    if (tid < 32) {
        s  = (tid < 8) ? red[0][tid] : 0.f;
        ss = (tid < 8) ? red[1][tid] : 0.f;
        #pragma unroll
        for (int o = 4; o > 0; o >>= 1) {
            s  += __shfl_down_sync(0xffffffffu, s,  o);
            ss += __shfl_down_sync(0xffffffffu, ss, o);
        }
        if (tid == 0) { red[0][0] = s; red[1][0] = ss; }
    }
    __syncthreads();
    float mean = red[0][0] * (1.f / D_);
    float var  = red[1][0] * (1.f / D_) - mean * mean;
    float rstd = rsqrtf(var + 1e-5f);
    float4 gv = *(const float4*)(g + c);
    float4 bv = *(const float4*)(b + c);
    float o0 = (xv.x - mean) * rstd * gv.x + bv.x;
    float o1 = (xv.y - mean) * rstd * gv.y + bv.y;
    float o2 = (xv.z - mean) * rstd * gv.z + bv.z;
    float o3 = (xv.w - mean) * rstd * gv.w + bv.w;
    *(half2*)(out + (size_t)row * D_ + c)     = __floats2half2_rn(o0, o1);
    *(half2*)(out + (size_t)row * D_ + c + 2) = __floats2half2_rn(o2, o3);
}

// ---------------- mma / ldmatrix / cp.async helpers ----------------
__device__ __forceinline__ void mma_f16(float4& c,
                                        unsigned a0, unsigned a1, unsigned a2, unsigned a3,
                                        unsigned b0, unsigned b1)
{
    asm volatile("mma.sync.aligned.m16n8k16.row.col.f32.f16.f16.f32 "
                 "{%0,%1,%2,%3}, {%4,%5,%6,%7}, {%8,%9}, {%0,%1,%2,%3};"
                 : "+f"(c.x), "+f"(c.y), "+f"(c.z), "+f"(c.w)
                 : "r"(a0), "r"(a1), "r"(a2), "r"(a3), "r"(b0), "r"(b1));
}
__device__ __forceinline__ void ldsm4(unsigned& r0, unsigned& r1, unsigned& r2, unsigned& r3,
                                      const __half* p)
{
    uint32_t a = (uint32_t)__cvta_generic_to_shared(p);
    asm volatile("ldmatrix.sync.aligned.m8n8.x4.shared.b16 {%0,%1,%2,%3}, [%4];"
                 : "=r"(r0), "=r"(r1), "=r"(r2), "=r"(r3) : "r"(a));
}
__device__ __forceinline__ void ldsm4t(unsigned& r0, unsigned& r1, unsigned& r2, unsigned& r3,
                                       const __half* p)
{
    uint32_t a = (uint32_t)__cvta_generic_to_shared(p);
    asm volatile("ldmatrix.sync.aligned.m8n8.x4.trans.shared.b16 {%0,%1,%2,%3}, [%4];"
                 : "=r"(r0), "=r"(r1), "=r"(r2), "=r"(r3) : "r"(a));
}
__device__ __forceinline__ void cp16(const __half* smem_dst, const __half* gptr) {
    uint32_t a = (uint32_t)__cvta_generic_to_shared(smem_dst);
    asm volatile("cp.async.cg.shared.global [%0], [%1], 16;\n" :: "r"(a), "l"(gptr));
}
__device__ __forceinline__ void cp_commit() { asm volatile("cp.async.commit_group;\n"); }
template<int N>
__device__ __forceinline__ void cp_wait() { asm volatile("cp.async.wait_group %0;\n" :: "n"(N)); }

// ---------------- fp16 GEMM: 128x128 tile, 4 warps (64x64 warptile), BK=32 ----
// 3-stage cp.async pipeline, ONE __syncthreads per k-iter.
#define SPADH 40
#define STGH (2 * 128 * SPADH)           // halves per stage (A + B)
#define GSMEM (3 * STGH * (int)sizeof(__half))
template<bool GELU, bool RES, bool HOUT>
__global__ void __launch_bounds__(128) hgemm(const __half* __restrict__ A,
                                             const __half* __restrict__ W,
                                             const float* __restrict__ bias,
                                             const float* __restrict__ res,
                                             float* __restrict__ Cf,
                                             __half* __restrict__ Ch,
                                             int M, int N, int K)
{
    extern __shared__ __half smg[];

    int tid  = threadIdx.x;
    int warp = tid >> 5;
    int lane = tid & 31;
    int g = lane >> 2;
    int t = lane & 3;
    int wm = (warp >> 1) * 64;
    int wn = (warp & 1) * 64;

    int m0 = blockIdx.y * 128;
    int n0 = blockIdx.x * 128;

    // cp.async coords: 512 chunks of 8 halves per matrix, 4 per thread
    int lrow[4], lcb[4];
    #pragma unroll
    for (int u = 0; u < 4; u++) {
        int lin = tid + u * 128;
        lrow[u] = lin >> 2;
        lcb[u]  = (lin & 3) * 8;
    }

    int arow = (lane & 15);
    int acol = 8 * (lane >> 4);
    int brow = (lane & 7) + ((lane >> 4) << 3);
    int bcol = 8 * ((lane >> 3) & 1);

    float4 acc[4][8];
    #pragma unroll
    for (int i = 0; i < 4; i++)
        #pragma unroll
        for (int j = 0; j < 8; j++) acc[i][j] = make_float4(0.f, 0.f, 0.f, 0.f);

    // prologue: stages 0,1
    #pragma unroll
    for (int st = 0; st < 2; st++) {
        __half* As = smg + st * STGH;
        __half* Bs = As + 128 * SPADH;
        #pragma unroll
        for (int u = 0; u < 4; u++) {
            cp16(&As[lrow[u] * SPADH + lcb[u]],
                 A + (size_t)(m0 + lrow[u]) * K + st * 32 + lcb[u]);
            cp16(&Bs[lrow[u] * SPADH + lcb[u]],
                 W + (size_t)(n0 + lrow[u]) * K + st * 32 + lcb[u]);
        }
        cp_commit();
    }

    int niter = K >> 5;
    int sidx = 0;
    for (int kt = 0; kt < niter; kt++) {
        cp_wait<1>();
        __syncthreads();
        const __half* Ab = smg + sidx * STGH;
        const __half* Bb = Ab + 128 * SPADH;

        #pragma unroll
        for (int kk = 0; kk < 32; kk += 16) {
            unsigned af[4][4];
            #pragma unroll
            for (int i = 0; i < 4; i++)
                ldsm4(af[i][0], af[i][1], af[i][2], af[i][3],
                      &Ab[(wm + 16 * i + arow) * SPADH + kk + acol]);
            unsigned bf[8][2];
            #pragma unroll
            for (int jj = 0; jj < 4; jj++)
                ldsm4(bf[2 * jj][0], bf[2 * jj][1], bf[2 * jj + 1][0], bf[2 * jj + 1][1],
                      &Bb[(wn + 16 * jj + brow) * SPADH + kk + bcol]);
            #pragma unroll
            for (int i = 0; i < 4; i++)
                #pragma unroll
                for (int j = 0; j < 8; j++)
                    mma_f16(acc[i][j], af[i][0], af[i][1], af[i][2], af[i][3],
                            bf[j][0], bf[j][1]);
        }

        // issue loads for kt+2 into stage (sidx+2)%3 — safe: distinct from
        // compute stage (sidx) and in-flight load stage (sidx+1); all warps
        // passed this iter's barrier, so its previous contents were consumed.
        int j2 = kt + 2;
        if (j2 < niter) {
            int s2 = sidx + 2; if (s2 >= 3) s2 -= 3;
            __half* As = smg + s2 * STGH;
            __half* Bs = As + 128 * SPADH;
            int k0n = j2 * 32;
            #pragma unroll
            for (int u = 0; u < 4; u++) {
                cp16(&As[lrow[u] * SPADH + lcb[u]],
                     A + (size_t)(m0 + lrow[u]) * K + k0n + lcb[u]);
                cp16(&Bs[lrow[u] * SPADH + lcb[u]],
                     W + (size_t)(n0 + lrow[u]) * K + k0n + lcb[u]);
            }
        }
        cp_commit();
        sidx++; if (sidx == 3) sidx = 0;
    }

    #pragma unroll
    for (int i = 0; i < 4; i++) {
        int r0 = m0 + wm + 16 * i + g;
        int r1 = r0 + 8;
        #pragma unroll
        for (int j = 0; j < 8; j++) {
            int col = n0 + wn + 8 * j + 2 * t;
            float b0 = bias[col], b1 = bias[col + 1];
            float v0 = acc[i][j].x + b0;
            float v1 = acc[i][j].y + b1;
            float v2 = acc[i][j].z + b0;
            float v3 = acc[i][j].w + b1;
            if (RES) {
                const float* rp0 = res + (size_t)r0 * N + col;
                const float* rp1 = res + (size_t)r1 * N + col;
                v0 += rp0[0]; v1 += rp0[1]; v2 += rp1[0]; v3 += rp1[1];
            }
            if (GELU) {
                v0 *= normcdff(v0); v1 *= normcdff(v1);
                v2 *= normcdff(v2); v3 *= normcdff(v3);
            }
            if (HOUT) {
                *(half2*)(Ch + (size_t)r0 * N + col) = __floats2half2_rn(v0, v1);
                *(half2*)(Ch + (size_t)r1 * N + col) = __floats2half2_rn(v2, v3);
            } else {
                *(float2*)(Cf + (size_t)r0 * N + col) = make_float2(v0, v1);
                *(float2*)(Cf + (size_t)r1 * N + col) = make_float2(v2, v3);
            }
        }
    }
}

// ---------------- fp16 flash attention (R7-proven, packed qkv) ----------------
#define FSP 72
__global__ void __launch_bounds__(128) flash_h(const __half* __restrict__ qkv,
                                               __half* __restrict__ o)
{
    extern __shared__ __half smh[];
    __half* Qs = smh;
    __half* Ks = Qs + 128 * FSP;
    __half* Vs = Ks + 64 * FSP;
    __half* Ps = Vs + 64 * FSP;

    int tid  = threadIdx.x;
    int warp = tid >> 5;
    int lane = tid & 31;
    int g = lane >> 2;
    int t = lane & 3;

    int bh = blockIdx.y;
    int b  = bh >> 4;
    int h  = bh & 15;
    int qt0 = blockIdx.x * 128;
    size_t qbase = ((size_t)b * T_) * QKVN + (size_t)h * DH_;
    size_t kbase = qbase + D_;
    size_t vbase = qbase + 2 * D_;
    size_t obase = ((size_t)b * T_) * D_ + (size_t)h * DH_;

    int arow = (lane & 15);
    int acol = 8 * (lane >> 4);
    int brow = (lane & 7) + ((lane >> 4) << 3);
    int bcol = 8 * ((lane >> 3) & 1);
    int vrow = (lane & 7) + (((lane >> 3) & 1) << 3);
    int vcol = 8 * (lane >> 4);

    {
        half2 sc = __float2half2_rn(0.125f);
        #pragma unroll
        for (int it = 0; it < 8; it++) {
            int lin = tid + it * 128;
            int row = lin >> 3;
            int cb  = (lin & 7) * 8;
            uint4 u = *(const uint4*)(qkv + qbase + (size_t)(qt0 + row) * QKVN + cb);
            half2* hp = (half2*)&u;
            hp[0] = __hmul2(hp[0], sc); hp[1] = __hmul2(hp[1], sc);
            hp[2] = __hmul2(hp[2], sc); hp[3] = __hmul2(hp[3], sc);
            *(uint4*)&Qs[row * FSP + cb] = u;
        }
    }
    __syncthreads();

    int r0w = warp * 32;

    unsigned qf[2][4][4];
    #pragma unroll
    for (int mb = 0; mb < 2; mb++)
        #pragma unroll
        for (int ks = 0; ks < 4; ks++)
            ldsm4(qf[mb][ks][0], qf[mb][ks][1], qf[mb][ks][2], qf[mb][ks][3],
                  &Qs[(r0w + 16 * mb + arow) * FSP + ks * 16 + acol]);

    float m_i[4] = {-1e30f, -1e30f, -1e30f, -1e30f};
    float l_i[4] = {0.f, 0.f, 0.f, 0.f};
    float4 oacc[2][8];
    #pragma unroll
    for (int mb = 0; mb < 2; mb++)
        #pragma unroll
        for (int nb = 0; nb < 8; nb++) oacc[mb][nb] = make_float4(0.f, 0.f, 0.f, 0.f);

    for (int kt0 = 0; kt0 < T_; kt0 += 64) {
        __syncthreads();
        #pragma unroll
        for (int it = 0; it < 4; it++) {
            int lin = tid + it * 128;
            int row = lin >> 3;
            int cb  = (lin & 7) * 8;
            *(uint4*)&Ks[row * FSP + cb] =
                *(const uint4*)(qkv + kbase + (size_t)(kt0 + row) * QKVN + cb);
            *(uint4*)&Vs[row * FSP + cb] =
                *(const uint4*)(qkv + vbase + (size_t)(kt0 + row) * QKVN + cb);
        }
        __syncthreads();

        float4 sacc[2][8];
        #pragma unroll
        for (int mb = 0; mb < 2; mb++)
            #pragma unroll
            for (int nb = 0; nb < 8; nb++) sacc[mb][nb] = make_float4(0.f, 0.f, 0.f, 0.f);
        #pragma unroll
        for (int ks = 0; ks < 4; ks++) {
            unsigned bb[8][2];
            #pragma unroll
            for (int jj = 0; jj < 4; jj++)
                ldsm4(bb[2 * jj][0], bb[2 * jj][1], bb[2 * jj + 1][0], bb[2 * jj + 1][1],
                      &Ks[(16 * jj + brow) * FSP + ks * 16 + bcol]);
            #pragma unroll
            for (int mb = 0; mb < 2; mb++)
                #pragma unroll
                for (int nb = 0; nb < 8; nb++)
                    mma_f16(sacc[mb][nb], qf[mb][ks][0], qf[mb][ks][1],
                            qf[mb][ks][2], qf[mb][ks][3], bb[nb][0], bb[nb][1]);
        }

        #pragma unroll
        for (int mb = 0; mb < 2; mb++) {
            float mx0 = -1e30f, mx1 = -1e30f;
            #pragma unroll
            for (int nb = 0; nb < 8; nb++) {
                mx0 = fmaxf(mx0, fmaxf(sacc[mb][nb].x, sacc[mb][nb].y));
                mx1 = fmaxf(mx1, fmaxf(sacc[mb][nb].z, sacc[mb][nb].w));
            }
            mx0 = fmaxf(mx0, __shfl_xor_sync(0xffffffffu, mx0, 1));
            mx0 = fmaxf(mx0, __shfl_xor_sync(0xffffffffu, mx0, 2));
            mx1 = fmaxf(mx1, __shfl_xor_sync(0xffffffffu, mx1, 1));
            mx1 = fmaxf(mx1, __shfl_xor_sync(0xffffffffu, mx1, 2));

            float mn0 = fmaxf(m_i[2 * mb + 0], mx0);
            float mn1 = fmaxf(m_i[2 * mb + 1], mx1);
            float al0 = __expf(m_i[2 * mb + 0] - mn0);
            float al1 = __expf(m_i[2 * mb + 1] - mn1);
            m_i[2 * mb + 0] = mn0;
            m_i[2 * mb + 1] = mn1;

            float s0 = 0.f, s1 = 0.f;
            int rbase  = (r0w + mb * 16 + g) * FSP;
            int rbase8 = (r0w + mb * 16 + g + 8) * FSP;
            #pragma unroll
            for (int nb = 0; nb < 8; nb++) {
                float p0 = __expf(sacc[mb][nb].x - mn0);
                float p1 = __expf(sacc[mb][nb].y - mn0);
                float p2 = __expf(sacc[mb][nb].z - mn1);
                float p3 = __expf(sacc[mb][nb].w - mn1);
                s0 += p0 + p1; s1 += p2 + p3;
                int cc = nb * 8 + 2 * t;
                *(half2*)&Ps[rbase + cc]  = __floats2half2_rn(p0, p1);
                *(half2*)&Ps[rbase8 + cc] = __floats2half2_rn(p2, p3);
            }
            s0 += __shfl_xor_sync(0xffffffffu, s0, 1);
            s0 += __shfl_xor_sync(0xffffffffu, s0, 2);
            s1 += __shfl_xor_sync(0xffffffffu, s1, 1);
            s1 += __shfl_xor_sync(0xffffffffu, s1, 2);
            l_i[2 * mb + 0] = l_i[2 * mb + 0] * al0 + s0;
            l_i[2 * mb + 1] = l_i[2 * mb + 1] * al1 + s1;

            #pragma unroll
            for (int nb = 0; nb < 8; nb++) {
                oacc[mb][nb].x *= al0; oacc[mb][nb].y *= al0;
                oacc[mb][nb].z *= al1; oacc[mb][nb].w *= al1;
            }
        }
        __syncwarp();

        #pragma unroll
        for (int ks = 0; ks < 4; ks++) {
            unsigned pf[2][4];
            #pragma unroll
            for (int mb = 0; mb < 2; mb++)
                ldsm4(pf[mb][0], pf[mb][1], pf[mb][2], pf[mb][3],
                      &Ps[(r0w + 16 * mb + arow) * FSP + ks * 16 + acol]);
            unsigned vf[8][2];
            #pragma unroll
            for (int jj = 0; jj < 4; jj++)
                ldsm4t(vf[2 * jj][0], vf[2 * jj][1], vf[2 * jj + 1][0], vf[2 * jj + 1][1],
                       &Vs[(ks * 16 + vrow) * FSP + 16 * jj + vcol]);
            #pragma unroll
            for (int mb = 0; mb < 2; mb++)
                #pragma unroll
                for (int nb = 0; nb < 8; nb++)
                    mma_f16(oacc[mb][nb], pf[mb][0], pf[mb][1], pf[mb][2], pf[mb][3],
                            vf[nb][0], vf[nb][1]);
        }
    }

    #pragma unroll
    for (int mb = 0; mb < 2; mb++) {
        float inv0 = 1.f / l_i[2 * mb + 0];
        float inv1 = 1.f / l_i[2 * mb + 1];
        int row0 = qt0 + r0w + mb * 16 + g;
        int row1 = row0 + 8;
        #pragma unroll
        for (int nb = 0; nb < 8; nb++) {
            int cc = nb * 8 + 2 * t;
            *(half2*)(o + obase + (size_t)row0 * D_ + cc) =
                __floats2half2_rn(oacc[mb][nb].x * inv0, oacc[mb][nb].y * inv0);
            *(half2*)(o + obase + (size_t)row1 * D_ + cc) =
                __floats2half2_rn(oacc[mb][nb].z * inv1, oacc[mb][nb].w * inv1);
        }
    }
}

// ---------------- launch ----------------
extern "C" void kernel_launch(void* const* d_in, const int* in_sizes, int n_in,
                              void* d_out, int out_size)
{
    const float* x    = (const float*)d_in[0];
    const float* ln1g = (const float*)d_in[1];
    const float* ln1b = (const float*)d_in[2];
    const float* ln2g = (const float*)d_in[3];
    const float* ln2b = (const float*)d_in[4];
    const float* wq   = (const float*)d_in[5];
    const float* bq   = (const float*)d_in[6];
    const float* wk   = (const float*)d_in[7];
    const float* bk   = (const float*)d_in[8];
    const float* wv   = (const float*)d_in[9];
    const float* bv   = (const float*)d_in[10];
    const float* wo   = (const float*)d_in[11];
    const float* bo   = (const float*)d_in[12];
    const float* w1   = (const float*)d_in[13];
    const float* b1   = (const float*)d_in[14];
    const float* w2   = (const float*)d_in[15];
    const float* b2   = (const float*)d_in[16];
    float* out = (float*)d_out;

    void* p;
    cudaGetSymbolAddress(&p, g_hh);   __half* h    = (__half*)p;
    cudaGetSymbolAddress(&p, g_qkv);  __half* qkv  = (__half*)p;
    cudaGetSymbolAddress(&p, g_ah);   __half* att  = (__half*)p;
    cudaGetSymbolAddress(&p, g_fh);   __half* ff   = (__half*)p;
    cudaGetSymbolAddress(&p, g_x2);   float*  x2   = (float*)p;
    cudaGetSymbolAddress(&p, g_wh);   __half* wh   = (__half*)p;
    cudaGetSymbolAddress(&p, g_bqkv); float*  bqkv = (float*)p;

    const size_t MB1 = 1024 * 1024;
    __half* hwqkv = wh;
    __half* hwo   = wh + 3 * MB1;
    __half* hw1   = wh + 4 * MB1;
    __half* hw2   = wh + 8 * MB1;

    int flash_smem = (128 + 64 + 64 + 128) * FSP * (int)sizeof(__half);
    cudaFuncSetAttribute(flash_h, cudaFuncAttributeMaxDynamicSharedMemorySize, flash_smem);
    cudaFuncSetAttribute(hgemm<false, false, true >, cudaFuncAttributeMaxDynamicSharedMemorySize, GSMEM);
    cudaFuncSetAttribute(hgemm<false, true,  false>, cudaFuncAttributeMaxDynamicSharedMemorySize, GSMEM);
    cudaFuncSetAttribute(hgemm<true,  false, true >, cudaFuncAttributeMaxDynamicSharedMemorySize, GSMEM);

    w2h_all<<<(12 * SEG + 255) / 256, 256>>>(wq, wk, wv, wo, w1, w2, wh);
    bpack_k<<<(D_ + 255) / 256, 256>>>(bq, bk, bv, bqkv);

    dim3 gQKV(QKVN / 128, NT / 128);   // (24, 64)
    dim3 gD(D_ / 128, NT / 128);       // (8, 64)
    dim3 gF(FF_ / 128, NT / 128);      // (32, 64)

    ln_k<<<NT, 256>>>(x, ln1g, ln1b, h);
    hgemm<false, false, true ><<<gQKV, 128, GSMEM>>>(h, hwqkv, bqkv, nullptr, nullptr, qkv, NT, QKVN, D_);
    flash_h<<<dim3(T_ / 128, B_ * H_), 128, flash_smem>>>(qkv, att);
    hgemm<false, true,  false><<<gD, 128, GSMEM>>>(att, hwo, bo, x, x2, nullptr, NT, D_, D_);
    ln_k<<<NT, 256>>>(x2, ln2g, ln2b, h);
    hgemm<true,  false, true ><<<gF, 128, GSMEM>>>(h, hw1, b1, nullptr, nullptr, ff, NT, FF_, D_);
    hgemm<false, true,  false><<<gD, 128, GSMEM>>>(ff, hw2, b2, x2, out, nullptr, NT, D_, FF_);
}